// round 5
// baseline (speedup 1.0000x reference)
#include <cuda_runtime.h>
#include <cuda_bf16.h>
#include <math.h>
#include <stddef.h>
#include <stdint.h>

// Problem dims (fixed by the reference)
#define BB   8
#define SS   1024
#define DD   1024
#define HH   16
#define DHH  64
#define FF   4096
#define MR   (BB*SS)   // 8192 rows

// ---------------- scratch (device globals; no allocation allowed) ----------
__device__ float g_t1 [MR*DD];
__device__ float g_x1 [MR*DD];

// bf16 split buffers
__device__ __nv_bfloat16 g_ah[MR*DD];            // activation hi (x / ctx / x1)
__device__ __nv_bfloat16 g_al[MR*DD];            // activation lo
__device__ __nv_bfloat16 g_qh[MR*DD];
__device__ __nv_bfloat16 g_ql[MR*DD];
__device__ __nv_bfloat16 g_kh[MR*DD];
__device__ __nv_bfloat16 g_kl[MR*DD];
__device__ __nv_bfloat16 g_vh[MR*DD];
__device__ __nv_bfloat16 g_vl[MR*DD];
__device__ __nv_bfloat16 g_hh[(size_t)MR*FF];    // FFN hidden hi
__device__ __nv_bfloat16 g_hl[(size_t)MR*FF];    // FFN hidden lo
__device__ __nv_bfloat16 g_wh[(size_t)DD*FF];    // weight hi, [N,K]
__device__ __nv_bfloat16 g_wl[(size_t)DD*FF];    // weight lo, [N,K]

// ================= PTX helpers (compute_103-safe: sm_80 features only) =====
__device__ __forceinline__ uint32_t smem_u32(const void* p) {
    uint32_t a;
    asm("{ .reg .u64 t; cvta.to.shared.u64 t, %1; cvt.u32.u64 %0, t; }"
        : "=r"(a) : "l"(p));
    return a;
}
__device__ __forceinline__ uint32_t sw128(uint32_t o) {
    return o ^ ((o >> 3) & 0x70);
}
__device__ __forceinline__ void cp16(uint32_t s, const void* g) {
    asm volatile("cp.async.cg.shared.global [%0], [%1], 16;" :: "r"(s), "l"(g));
}
#define CP_COMMIT()  asm volatile("cp.async.commit_group;" ::: "memory")
#define CP_WAIT0()   asm volatile("cp.async.wait_group 0;" ::: "memory")
#define CP_WAIT1()   asm volatile("cp.async.wait_group 1;" ::: "memory")

__device__ __forceinline__ void ldsm4(uint32_t* r, uint32_t addr) {
    asm volatile("ldmatrix.sync.aligned.m8n8.x4.shared.b16 {%0,%1,%2,%3}, [%4];"
                 : "=r"(r[0]), "=r"(r[1]), "=r"(r[2]), "=r"(r[3]) : "r"(addr));
}
__device__ __forceinline__ void ldsm4t(uint32_t* r, uint32_t addr) {
    asm volatile("ldmatrix.sync.aligned.m8n8.x4.trans.shared.b16 {%0,%1,%2,%3}, [%4];"
                 : "=r"(r[0]), "=r"(r[1]), "=r"(r[2]), "=r"(r[3]) : "r"(addr));
}
// NOTE: non-volatile — pure dataflow, lets the scheduler interleave HMMAs.
__device__ __forceinline__ void mma16816(float* d, const uint32_t* a,
                                         const uint32_t* b) {
    asm("mma.sync.aligned.m16n8k16.row.col.f32.bf16.bf16.f32 "
        "{%0,%1,%2,%3}, {%4,%5,%6,%7}, {%8,%9}, {%0,%1,%2,%3};"
        : "+f"(d[0]), "+f"(d[1]), "+f"(d[2]), "+f"(d[3])
        : "r"(a[0]), "r"(a[1]), "r"(a[2]), "r"(a[3]),
          "r"(b[0]), "r"(b[1]));
}
// pack (v0,v1) into bf16x2 hi + bf16x2 lo-residual
__device__ __forceinline__ void pack_hl(float v0, float v1,
                                        uint32_t& hi, uint32_t& lo) {
    __nv_bfloat162 h = __floats2bfloat162_rn(v0, v1);
    float h0 = __bfloat162float(h.x), h1 = __bfloat162float(h.y);
    __nv_bfloat162 l = __floats2bfloat162_rn(v0 - h0, v1 - h1);
    hi = *(uint32_t*)&h;
    lo = *(uint32_t*)&l;
}

// ================= mma.sync GEMM ============================================
// C[M,N] = (Ah+Al)[M,K] @ (Bh+Bl)^T   (B stored [N,K] K-major) + bias
// 3-term bf16 emulation of fp32, TERM-MAJOR issue order (16 independent
// accumulators between reuses of the same acc).
#define G_STAGE  65536            // Ah 16K | Al 16K | Bh 16K | Bl 16K
#define G_SMEM   (2*G_STAGE)

template<int ACT, int SPLITOUT>
__global__ __launch_bounds__(256)
void gemm_mma(const __nv_bfloat16* __restrict__ Ah,
              const __nv_bfloat16* __restrict__ Al,
              const __nv_bfloat16* __restrict__ Bh,
              const __nv_bfloat16* __restrict__ Bl,
              const float* __restrict__ bias,
              float* __restrict__ C,
              __nv_bfloat16* __restrict__ Ch,
              __nv_bfloat16* __restrict__ Cl,
              int N, int K)
{
    extern __shared__ __align__(128) char smem[];
    const uint32_t sb = smem_u32(smem);
    const int tid  = threadIdx.x;
    const int wid  = tid >> 5;
    const int lane = tid & 31;
    const int wm   = wid & 3;
    const int wn   = wid >> 2;
    const int bc = blockIdx.x, br = blockIdx.y;

    const __nv_bfloat16* Ah_t = Ah + (size_t)br * 128 * K;
    const __nv_bfloat16* Al_t = Al + (size_t)br * 128 * K;
    const __nv_bfloat16* Bh_t = Bh + (size_t)bc * 128 * K;
    const __nv_bfloat16* Bl_t = Bl + (size_t)bc * 128 * K;
    const int NT = K >> 6;

    auto load_stage = [&](int kt, int s) {
        const uint32_t base = sb + s * G_STAGE;
        const int koff = kt * 64;
        #pragma unroll
        for (int t = 0; t < 4; t++) {
            int idx = t * 256 + tid;
            int row = idx >> 3, ch = idx & 7;
            uint32_t so = sw128((uint32_t)(row * 128 + ch * 16));
            size_t go = (size_t)row * K + koff + ch * 8;
            cp16(base +         so, Ah_t + go);
            cp16(base + 16384 + so, Al_t + go);
            cp16(base + 32768 + so, Bh_t + go);
            cp16(base + 49152 + so, Bl_t + go);
        }
        CP_COMMIT();
    };

    float acc[2][8][4];
    #pragma unroll
    for (int mi = 0; mi < 2; mi++)
        #pragma unroll
        for (int nj = 0; nj < 8; nj++)
            #pragma unroll
            for (int e = 0; e < 4; e++) acc[mi][nj][e] = 0.f;

    const int g = lane >> 3, r = lane & 7;

    load_stage(0, 0);

    for (int kt = 0; kt < NT; kt++) {
        const int buf = kt & 1;
        if (kt + 1 < NT) { load_stage(kt + 1, buf ^ 1); CP_WAIT1(); }
        else             { CP_WAIT0(); }
        __syncthreads();

        const uint32_t sA  = sb + buf * G_STAGE;
        const uint32_t sAl = sA + 16384;
        const uint32_t sBh = sA + 32768;
        const uint32_t sBl = sA + 49152;

        #pragma unroll
        for (int kc = 0; kc < 4; kc++) {
            // load ALL fragments for this k-chunk first
            uint32_t a_h[2][4], a_l[2][4];
            #pragma unroll
            for (int mi = 0; mi < 2; mi++) {
                int arow = wm * 32 + mi * 16 + r + ((g & 1) << 3);
                uint32_t off = sw128((uint32_t)(arow * 128 + kc * 32 +
                                                ((g >> 1) << 4)));
                ldsm4(a_h[mi], sA  + off);
                ldsm4(a_l[mi], sAl + off);
            }
            uint32_t b_h[4][4], b_l[4][4];
            #pragma unroll
            for (int np = 0; np < 4; np++) {
                int brow = wn * 64 + np * 16 + r + ((g >> 1) << 3);
                uint32_t off = sw128((uint32_t)(brow * 128 + kc * 32 +
                                                ((g & 1) << 4)));
                ldsm4(b_h[np], sBh + off);
                ldsm4(b_l[np], sBl + off);
            }
            // term 1: hh (16 independent accumulators)
            #pragma unroll
            for (int np = 0; np < 4; np++)
                #pragma unroll
                for (int t = 0; t < 2; t++)
                    #pragma unroll
                    for (int mi = 0; mi < 2; mi++)
                        mma16816(acc[mi][np * 2 + t], a_h[mi], &b_h[np][2 * t]);
            // term 2: lh
            #pragma unroll
            for (int np = 0; np < 4; np++)
                #pragma unroll
                for (int t = 0; t < 2; t++)
                    #pragma unroll
                    for (int mi = 0; mi < 2; mi++)
                        mma16816(acc[mi][np * 2 + t], a_l[mi], &b_h[np][2 * t]);
            // term 3: hl
            #pragma unroll
            for (int np = 0; np < 4; np++)
                #pragma unroll
                for (int t = 0; t < 2; t++)
                    #pragma unroll
                    for (int mi = 0; mi < 2; mi++)
                        mma16816(acc[mi][np * 2 + t], a_h[mi], &b_l[np][2 * t]);
        }
        __syncthreads();
    }

    const int cbase = bc * 128 + wn * 64 + (lane & 3) * 2;
    const int rbase = br * 128 + wm * 32 + (lane >> 2);
    #pragma unroll
    for (int mi = 0; mi < 2; mi++) {
        #pragma unroll
        for (int nj = 0; nj < 8; nj++) {
            int c = cbase + nj * 8;
            float2 bv = *(const float2*)(bias + c);
            float v0 = acc[mi][nj][0] + bv.x;
            float v1 = acc[mi][nj][1] + bv.y;
            float v2 = acc[mi][nj][2] + bv.x;
            float v3 = acc[mi][nj][3] + bv.y;
            if (ACT) {
                v0 = fmaxf(v0, 0.f); v1 = fmaxf(v1, 0.f);
                v2 = fmaxf(v2, 0.f); v3 = fmaxf(v3, 0.f);
            }
            size_t i0 = (size_t)(rbase + mi * 16)     * N + c;
            size_t i1 = (size_t)(rbase + mi * 16 + 8) * N + c;
            if (SPLITOUT) {
                uint32_t h0, l0, h1, l1;
                pack_hl(v0, v1, h0, l0);
                pack_hl(v2, v3, h1, l1);
                *(uint32_t*)(Ch + i0) = h0;
                *(uint32_t*)(Ch + i1) = h1;
                *(uint32_t*)(Cl + i0) = l0;
                *(uint32_t*)(Cl + i1) = l1;
            } else {
                float2 o0; o0.x = v0; o0.y = v1;
                float2 o1; o1.x = v2; o1.y = v3;
                *(float2*)(C + i0) = o0;
                *(float2*)(C + i1) = o1;
            }
        }
    }
}

// ================= Flash attention on tensor cores ==========================
// Block = (b, h, 128-query tile). 8 warps, warp w owns query rows [16w,16w+16).
// Term-major mma issue order in both QK^T and PV.
#define A_QH   0
#define A_QL   16384
#define A_ST   32768            // 2 stages x (Kh 8K | Kl 8K | Vh 8K | Vl 8K)
#define A_MK   98304            // 2 x 256 B mask
#define A_SMEM (98304 + 512)

__global__ __launch_bounds__(256)
void attn_mma(const __nv_bfloat16* __restrict__ qh,
              const __nv_bfloat16* __restrict__ ql,
              const __nv_bfloat16* __restrict__ kh,
              const __nv_bfloat16* __restrict__ kl,
              const __nv_bfloat16* __restrict__ vh,
              const __nv_bfloat16* __restrict__ vl,
              const float* __restrict__ mask,
              __nv_bfloat16* __restrict__ ch,
              __nv_bfloat16* __restrict__ cl)
{
    extern __shared__ __align__(128) char smem[];
    const uint32_t sb = smem_u32(smem);
    const int tid  = threadIdx.x;
    const int wid  = tid >> 5;
    const int lane = tid & 31;
    const int g    = lane >> 3, r8 = lane & 7;
    const int c2   = (lane & 3) * 2;

    const int qt = blockIdx.x;              // 0..7
    const int bh = blockIdx.y;              // 0..127
    const int b  = bh >> 4;
    const int h  = bh & 15;

    const size_t qrow0 = (size_t)b * SS + (size_t)qt * 128;
    const __nv_bfloat16* qhg = qh + qrow0 * DD + h * DHH;
    const __nv_bfloat16* qlg = ql + qrow0 * DD + h * DHH;
    const __nv_bfloat16* khg = kh + (size_t)b * SS * DD + h * DHH;
    const __nv_bfloat16* klg = kl + (size_t)b * SS * DD + h * DHH;
    const __nv_bfloat16* vhg = vh + (size_t)b * SS * DD + h * DHH;
    const __nv_bfloat16* vlg = vl + (size_t)b * SS * DD + h * DHH;
    const float* mkg = mask + (size_t)b * SS;

    auto load_kv = [&](int t, int s) {
        const uint32_t base = sb + A_ST + s * 32768;
        const size_t koff = (size_t)(t * 64) * DD;
        #pragma unroll
        for (int it = 0; it < 8; it++) {
            int idx = it * 256 + tid;            // 0..2047
            int mat = idx >> 9;                  // 0..3: Kh,Kl,Vh,Vl
            int sub = idx & 511;
            int row = sub >> 3, chk = sub & 7;
            uint32_t so = sw128((uint32_t)(row * 128 + chk * 16));
            size_t go = koff + (size_t)row * DD + chk * 8;
            const __nv_bfloat16* src =
                (mat == 0) ? khg : (mat == 1) ? klg : (mat == 2) ? vhg : vlg;
            cp16(base + mat * 8192 + so, src + go);
        }
        if (tid < 16)
            cp16(sb + A_MK + s * 256 + tid * 16, mkg + t * 64 + tid * 4);
        CP_COMMIT();
    };

    // Q tile load (with stage 0)
    #pragma unroll
    for (int it = 0; it < 8; it++) {
        int idx = it * 256 + tid;                // 0..2047
        int mat = idx >> 10;                     // 0: qh, 1: ql
        int sub = idx & 1023;
        int row = sub >> 3, chk = sub & 7;
        uint32_t so = sw128((uint32_t)(row * 128 + chk * 16));
        size_t go = (size_t)row * DD + chk * 8;
        cp16(sb + (mat ? A_QL : A_QH) + so, (mat ? qlg : qhg) + go);
    }
    load_kv(0, 0);

    float mA = -INFINITY, mB = -INFINITY, lA = 0.f, lB = 0.f;
    float O[8][4];
    #pragma unroll
    for (int j = 0; j < 8; j++)
        #pragma unroll
        for (int e = 0; e < 4; e++) O[j][e] = 0.f;

    #pragma unroll 1
    for (int t = 0; t < 16; t++) {
        const int buf = t & 1;
        if (t + 1 < 16) { load_kv(t + 1, buf ^ 1); CP_WAIT1(); }
        else            { CP_WAIT0(); }
        __syncthreads();

        const uint32_t sKh = sb + A_ST + buf * 32768;
        const uint32_t sKl = sKh + 8192;
        const uint32_t sVh = sKh + 16384;
        const uint32_t sVl = sKh + 24576;
        const float* mkv = (const float*)(smem + A_MK + buf * 256);

        // ---- S = Q @ K^T (3-term, term-major) ----
        float s_[8][4];
        #pragma unroll
        for (int j = 0; j < 8; j++)
            #pragma unroll
            for (int e = 0; e < 4; e++) s_[j][e] = 0.f;

        #pragma unroll
        for (int kc = 0; kc < 4; kc++) {
            uint32_t aqh[4], aql[4];
            {
                int arow = wid * 16 + r8 + ((g & 1) << 3);
                uint32_t off = sw128((uint32_t)(arow * 128 + kc * 32 +
                                                ((g >> 1) << 4)));
                ldsm4(aqh, sb + A_QH + off);
                ldsm4(aql, sb + A_QL + off);
            }
            uint32_t bkh[4][4], bkl[4][4];
            #pragma unroll
            for (int np = 0; np < 4; np++) {
                int brow = np * 16 + r8 + ((g >> 1) << 3);
                uint32_t off = sw128((uint32_t)(brow * 128 + kc * 32 +
                                                ((g & 1) << 4)));
                ldsm4(bkh[np], sKh + off);
                ldsm4(bkl[np], sKl + off);
            }
            #pragma unroll
            for (int np = 0; np < 4; np++)
                #pragma unroll
                for (int t2 = 0; t2 < 2; t2++)
                    mma16816(s_[np * 2 + t2], aqh, &bkh[np][2 * t2]);
            #pragma unroll
            for (int np = 0; np < 4; np++)
                #pragma unroll
                for (int t2 = 0; t2 < 2; t2++)
                    mma16816(s_[np * 2 + t2], aql, &bkh[np][2 * t2]);
            #pragma unroll
            for (int np = 0; np < 4; np++)
                #pragma unroll
                for (int t2 = 0; t2 < 2; t2++)
                    mma16816(s_[np * 2 + t2], aqh, &bkl[np][2 * t2]);
        }

        // ---- scale + mask, row max ----
        float tmA = -INFINITY, tmB = -INFINITY;
        #pragma unroll
        for (int j = 0; j < 8; j++) {
            float mk0 = mkv[j * 8 + c2]     * (-1e9f);
            float mk1 = mkv[j * 8 + c2 + 1] * (-1e9f);
            s_[j][0] = s_[j][0] * 0.125f + mk0;
            s_[j][1] = s_[j][1] * 0.125f + mk1;
            s_[j][2] = s_[j][2] * 0.125f + mk0;
            s_[j][3] = s_[j][3] * 0.125f + mk1;
            tmA = fmaxf(tmA, fmaxf(s_[j][0], s_[j][1]));
            tmB = fmaxf(tmB, fmaxf(s_[j][2], s_[j][3]));
        }
        tmA = fmaxf(tmA, __shfl_xor_sync(0xffffffffu, tmA, 1));
        tmA = fmaxf(tmA, __shfl_xor_sync(0xffffffffu, tmA, 2));
        tmB = fmaxf(tmB, __shfl_xor_sync(0xffffffffu, tmB, 1));
        tmB = fmaxf(tmB, __shfl_xor_sync(0xffffffffu, tmB, 2));

        const float nmA = fmaxf(mA, tmA), nmB = fmaxf(mB, tmB);
        const float fA = __expf(mA - nmA), fB = __expf(mB - nmB);

        // ---- p = exp(s - m), row sum ----
        float sumA = 0.f, sumB = 0.f;
        #pragma unroll
        for (int j = 0; j < 8; j++) {
            s_[j][0] = __expf(s_[j][0] - nmA);
            s_[j][1] = __expf(s_[j][1] - nmA);
            s_[j][2] = __expf(s_[j][2] - nmB);
            s_[j][3] = __expf(s_[j][3] - nmB);
            sumA += s_[j][0] + s_[j][1];
            sumB += s_[j][2] + s_[j][3];
        }
        sumA += __shfl_xor_sync(0xffffffffu, sumA, 1);
        sumA += __shfl_xor_sync(0xffffffffu, sumA, 2);
        sumB += __shfl_xor_sync(0xffffffffu, sumB, 1);
        sumB += __shfl_xor_sync(0xffffffffu, sumB, 2);
        lA = lA * fA + sumA;  mA = nmA;
        lB = lB * fB + sumB;  mB = nmB;

        // ---- rescale O ----
        #pragma unroll
        for (int j = 0; j < 8; j++) {
            O[j][0] *= fA; O[j][1] *= fA;
            O[j][2] *= fB; O[j][3] *= fB;
        }

        // ---- O += P @ V (3-term, term-major) ----
        #pragma unroll
        for (int c = 0; c < 4; c++) {
            uint32_t ap_h[4], ap_l[4];
            pack_hl(s_[2 * c][0],     s_[2 * c][1],     ap_h[0], ap_l[0]);
            pack_hl(s_[2 * c][2],     s_[2 * c][3],     ap_h[1], ap_l[1]);
            pack_hl(s_[2 * c + 1][0], s_[2 * c + 1][1], ap_h[2], ap_l[2]);
            pack_hl(s_[2 * c + 1][2], s_[2 * c + 1][3], ap_h[3], ap_l[3]);
            uint32_t bvh[4][4], bvl[4][4];
            #pragma unroll
            for (int np2 = 0; np2 < 4; np2++) {
                int vrow = c * 16 + r8 + ((g & 1) << 3);
                uint32_t off = sw128((uint32_t)(vrow * 128 + np2 * 32 +
                                                ((g >> 1) << 4)));
                ldsm4t(bvh[np2], sVh + off);
                ldsm4t(bvl[np2], sVl + off);
            }
            #pragma unroll
            for (int np2 = 0; np2 < 4; np2++)
                #pragma unroll
                for (int t2 = 0; t2 < 2; t2++)
                    mma16816(O[np2 * 2 + t2], ap_h, &bvh[np2][2 * t2]);
            #pragma unroll
            for (int np2 = 0; np2 < 4; np2++)
                #pragma unroll
                for (int t2 = 0; t2 < 2; t2++)
                    mma16816(O[np2 * 2 + t2], ap_l, &bvh[np2][2 * t2]);
            #pragma unroll
            for (int np2 = 0; np2 < 4; np2++)
                #pragma unroll
                for (int t2 = 0; t2 < 2; t2++)
                    mma16816(O[np2 * 2 + t2], ap_h, &bvl[np2][2 * t2]);
        }
        __syncthreads();
    }

    // ---- normalize, split, write ctx ----
    const float liA = 1.f / lA, liB = 1.f / lB;
    const size_t rowA = qrow0 + wid * 16 + (lane >> 2);
    const size_t rowB = rowA + 8;
    const int    colb = h * DHH + c2;
    #pragma unroll
    for (int j = 0; j < 8; j++) {
        uint32_t hi, lo;
        pack_hl(O[j][0] * liA, O[j][1] * liA, hi, lo);
        *(uint32_t*)(ch + rowA * DD + colb + j * 8) = hi;
        *(uint32_t*)(cl + rowA * DD + colb + j * 8) = lo;
        pack_hl(O[j][2] * liB, O[j][3] * liB, hi, lo);
        *(uint32_t*)(ch + rowB * DD + colb + j * 8) = hi;
        *(uint32_t*)(cl + rowB * DD + colb + j * 8) = lo;
    }
}

// ================= fp32 -> bf16 hi/lo split =================================
__global__ __launch_bounds__(256) void split_kernel(
    const float4* __restrict__ in, __nv_bfloat162* __restrict__ oh,
    __nv_bfloat162* __restrict__ ol, int n4)
{
    int i = blockIdx.x * 256 + threadIdx.x;
    if (i >= n4) return;
    float4 v = in[i];
    uint32_t h0, l0, h1, l1;
    pack_hl(v.x, v.y, h0, l0);
    pack_hl(v.z, v.w, h1, l1);
    oh[2 * i]     = *(__nv_bfloat162*)&h0;
    oh[2 * i + 1] = *(__nv_bfloat162*)&h1;
    ol[2 * i]     = *(__nv_bfloat162*)&l0;
    ol[2 * i + 1] = *(__nv_bfloat162*)&l1;
}

// W[K,N] fp32 -> hi/lo bf16 [N,K] (transpose + split)
__global__ __launch_bounds__(256) void split_tr_kernel(
    const float* __restrict__ W, __nv_bfloat16* __restrict__ oh,
    __nv_bfloat16* __restrict__ ol, int K, int N)
{
    __shared__ float t[32][33];
    const int bx = blockIdx.x, by = blockIdx.y;
    const int tx = threadIdx.x, ty = threadIdx.y;   // 32 x 8
    #pragma unroll
    for (int i = 0; i < 4; i++) {
        int rr = ty + i * 8;
        t[rr][tx] = W[(size_t)(by * 32 + rr) * N + bx * 32 + tx];
    }
    __syncthreads();
    #pragma unroll
    for (int i = 0; i < 4; i++) {
        int rr = ty + i * 8;
        float v = t[tx][rr];
        __nv_bfloat16 h = __float2bfloat16(v);
        size_t o = (size_t)(bx * 32 + rr) * K + by * 32 + tx;
        oh[o] = h;
        ol[o] = __float2bfloat16(v - __bfloat162float(h));
    }
}

// ================= residual + LayerNorm (optional fused bf16 split) ========
template<int SPL>
__global__ __launch_bounds__(256) void residual_ln_kernel(
    const float* __restrict__ X, const float* __restrict__ Y,
    const float* __restrict__ g, const float* __restrict__ beta,
    float* __restrict__ out,
    __nv_bfloat16* __restrict__ oh, __nv_bfloat16* __restrict__ ol)
{
    __shared__ float ws[8], ws2[8];
    const int row = blockIdx.x;
    const int tid = threadIdx.x;
    const int lane = tid & 31, warp = tid >> 5;
    const float* px = X + (size_t)row * DD;
    const float* py = Y + (size_t)row * DD;

    float v[4];
    float s = 0.f, s2 = 0.f;
    #pragma unroll
    for (int l = 0; l < 4; l++) {
        int c = tid + l * 256;
        float t = px[c] + py[c];
        v[l] = t; s += t; s2 += t * t;
    }
    #pragma unroll
    for (int off = 16; off; off >>= 1) {
        s  += __shfl_xor_sync(0xffffffffu, s,  off);
        s2 += __shfl_xor_sync(0xffffffffu, s2, off);
    }
    if (lane == 0) { ws[warp] = s; ws2[warp] = s2; }
    __syncthreads();
    if (warp == 0) {
        s  = (lane < 8) ? ws[lane]  : 0.f;
        s2 = (lane < 8) ? ws2[lane] : 0.f;
        #pragma unroll
        for (int off = 4; off; off >>= 1) {
            s  += __shfl_xor_sync(0xffffffffu, s,  off);
            s2 += __shfl_xor_sync(0xffffffffu, s2, off);
        }
        if (lane == 0) { ws[0] = s; ws2[0] = s2; }
    }
    __syncthreads();
    float mu  = ws[0] * (1.f / 1024.f);
    float var = fmaxf(ws2[0] * (1.f / 1024.f) - mu * mu, 0.f);
    float rstd = rsqrtf(var + 1e-6f);
    #pragma unroll
    for (int l = 0; l < 4; l++) {
        int c = tid + l * 256;
        float rv = g[c] * (v[l] - mu) * rstd + beta[c];
        out[(size_t)row * DD + c] = rv;
        if (SPL) {
            __nv_bfloat16 h = __float2bfloat16(rv);
            oh[(size_t)row * DD + c] = h;
            ol[(size_t)row * DD + c] =
                __float2bfloat16(rv - __bfloat162float(h));
        }
    }
}

// ================= launch ===================================================
extern "C" void kernel_launch(void* const* d_in, const int* in_sizes, int n_in,
                              void* d_out, int out_size)
{
    const float* x    = (const float*)d_in[0];
    const float* mask = (const float*)d_in[1];
    const float* Wq   = (const float*)d_in[2];
    const float* bq   = (const float*)d_in[3];
    const float* Wk   = (const float*)d_in[4];
    const float* bk   = (const float*)d_in[5];
    const float* Wv   = (const float*)d_in[6];
    const float* bv   = (const float*)d_in[7];
    const float* Wo   = (const float*)d_in[8];
    const float* bo   = (const float*)d_in[9];
    const float* g1   = (const float*)d_in[10];
    const float* be1  = (const float*)d_in[11];
    const float* W1   = (const float*)d_in[12];
    const float* bf1  = (const float*)d_in[13];
    const float* W2   = (const float*)d_in[14];
    const float* bf2  = (const float*)d_in[15];
    const float* g2   = (const float*)d_in[16];
    const float* be2  = (const float*)d_in[17];
    float* out = (float*)d_out;

    float *t1, *x1;
    __nv_bfloat16 *ah, *al, *qh, *ql, *kh, *kl, *vh, *vl, *hh, *hl, *wh, *wl;
    cudaGetSymbolAddress((void**)&t1,  g_t1);
    cudaGetSymbolAddress((void**)&x1,  g_x1);
    cudaGetSymbolAddress((void**)&ah,  g_ah);
    cudaGetSymbolAddress((void**)&al,  g_al);
    cudaGetSymbolAddress((void**)&qh,  g_qh);
    cudaGetSymbolAddress((void**)&ql,  g_ql);
    cudaGetSymbolAddress((void**)&kh,  g_kh);
    cudaGetSymbolAddress((void**)&kl,  g_kl);
    cudaGetSymbolAddress((void**)&vh,  g_vh);
    cudaGetSymbolAddress((void**)&vl,  g_vl);
    cudaGetSymbolAddress((void**)&hh,  g_hh);
    cudaGetSymbolAddress((void**)&hl,  g_hl);
    cudaGetSymbolAddress((void**)&wh,  g_wh);
    cudaGetSymbolAddress((void**)&wl,  g_wl);

    cudaFuncSetAttribute(attn_mma,
                         cudaFuncAttributeMaxDynamicSharedMemorySize, A_SMEM);
    cudaFuncSetAttribute(gemm_mma<0, 0>,
                         cudaFuncAttributeMaxDynamicSharedMemorySize, G_SMEM);
    cudaFuncSetAttribute(gemm_mma<0, 1>,
                         cudaFuncAttributeMaxDynamicSharedMemorySize, G_SMEM);
    cudaFuncSetAttribute(gemm_mma<1, 1>,
                         cudaFuncAttributeMaxDynamicSharedMemorySize, G_SMEM);

    const dim3 trDD(DD / 32, DD / 32);
    const dim3 trDF(FF / 32, DD / 32);   // W1: K=DD, N=FF
    const dim3 trFD(DD / 32, FF / 32);   // W2: K=FF, N=DD
    const dim3 tb(32, 8);
    const dim3 gD(DD / 128, MR / 128);   // (8, 64)
    const dim3 gF(FF / 128, MR / 128);   // (32, 64)

    // split x -> ah/al
    split_kernel<<<(MR * DD / 4 + 255) / 256, 256>>>(
        (const float4*)x, (__nv_bfloat162*)ah, (__nv_bfloat162*)al, MR * DD / 4);

    // QKV projections: epilogue emits split bf16 q/k/v directly
    split_tr_kernel<<<trDD, tb>>>(Wq, wh, wl, DD, DD);
    gemm_mma<0, 1><<<gD, 256, G_SMEM>>>(ah, al, wh, wl, bq, nullptr, qh, ql, DD, DD);
    split_tr_kernel<<<trDD, tb>>>(Wk, wh, wl, DD, DD);
    gemm_mma<0, 1><<<gD, 256, G_SMEM>>>(ah, al, wh, wl, bk, nullptr, kh, kl, DD, DD);
    split_tr_kernel<<<trDD, tb>>>(Wv, wh, wl, DD, DD);
    gemm_mma<0, 1><<<gD, 256, G_SMEM>>>(ah, al, wh, wl, bv, nullptr, vh, vl, DD, DD);

    // fused tensor-core attention -> split ctx into ah/al
    attn_mma<<<dim3(8, 128), 256, A_SMEM>>>(qh, ql, kh, kl, vh, vl, mask, ah, al);

    // output projection + residual LN (LN emits split x1 for FFN1)
    split_tr_kernel<<<trDD, tb>>>(Wo, wh, wl, DD, DD);
    gemm_mma<0, 0><<<gD, 256, G_SMEM>>>(ah, al, wh, wl, bo, t1, nullptr, nullptr, DD, DD);
    residual_ln_kernel<1><<<MR, 256>>>(x, t1, g1, be1, x1, ah, al);

    // FFN1: relu(x1 @ W1 + bf1), epilogue writes split bf16 hidden directly
    split_tr_kernel<<<trDF, tb>>>(W1, wh, wl, DD, FF);
    gemm_mma<1, 1><<<gF, 256, G_SMEM>>>(ah, al, wh, wl, bf1, nullptr, hh, hl, FF, DD);

    // FFN2 + residual LN
    split_tr_kernel<<<trFD, tb>>>(W2, wh, wl, FF, DD);
    gemm_mma<0, 0><<<gD, 256, G_SMEM>>>(hh, hl, wh, wl, bf2, t1, nullptr, nullptr, DD, FF);
    residual_ln_kernel<0><<<MR, 256>>>(x1, t1, g2, be2, out, nullptr, nullptr);
}

// round 6
// speedup vs baseline: 1.1978x; 1.1978x over previous
#include <cuda_runtime.h>
#include <cuda_fp16.h>
#include <math.h>
#include <stddef.h>
#include <stdint.h>

// Problem dims (fixed by the reference)
#define BB   8
#define SS   1024
#define DD   1024
#define HH   16
#define DHH  64
#define FF   4096
#define MR   (BB*SS)   // 8192 rows

// ---------------- scratch (device globals; no allocation allowed) ----------
__device__ float g_t1 [MR*DD];
__device__ float g_x1 [MR*DD];

// fp16 split buffers
__device__ __half g_ah[MR*DD];            // activation hi (x / ctx / x1)
__device__ __half g_al[MR*DD];            // activation lo
__device__ __half g_qh[MR*DD];
__device__ __half g_ql[MR*DD];
__device__ __half g_kh[MR*DD];
__device__ __half g_kl[MR*DD];
__device__ __half g_vh[MR*DD];
__device__ __half g_vl[MR*DD];
__device__ __half g_hh[(size_t)MR*FF];    // FFN hidden hi
__device__ __half g_hl[(size_t)MR*FF];    // FFN hidden lo
// per-weight buffers, [N,K] K-major
__device__ __half g_wqh[DD*DD];
__device__ __half g_wql[DD*DD];
__device__ __half g_wkh[DD*DD];
__device__ __half g_wkl[DD*DD];
__device__ __half g_wvh[DD*DD];
__device__ __half g_wvl[DD*DD];
__device__ __half g_woh[DD*DD];
__device__ __half g_wol[DD*DD];
__device__ __half g_w1h[(size_t)DD*FF];   // FFN weights: hi only (2-term)
__device__ __half g_w2h[(size_t)FF*DD];

// ================= PTX helpers (compute_103-safe: sm_80 features only) =====
__device__ __forceinline__ uint32_t smem_u32(const void* p) {
    uint32_t a;
    asm("{ .reg .u64 t; cvta.to.shared.u64 t, %1; cvt.u32.u64 %0, t; }"
        : "=r"(a) : "l"(p));
    return a;
}
__device__ __forceinline__ uint32_t sw128(uint32_t o) {
    return o ^ ((o >> 3) & 0x70);
}
__device__ __forceinline__ void cp16(uint32_t s, const void* g) {
    asm volatile("cp.async.cg.shared.global [%0], [%1], 16;" :: "r"(s), "l"(g));
}
#define CP_COMMIT()  asm volatile("cp.async.commit_group;" ::: "memory")
#define CP_WAIT0()   asm volatile("cp.async.wait_group 0;" ::: "memory")
#define CP_WAIT1()   asm volatile("cp.async.wait_group 1;" ::: "memory")

__device__ __forceinline__ void ldsm4(uint32_t* r, uint32_t addr) {
    asm volatile("ldmatrix.sync.aligned.m8n8.x4.shared.b16 {%0,%1,%2,%3}, [%4];"
                 : "=r"(r[0]), "=r"(r[1]), "=r"(r[2]), "=r"(r[3]) : "r"(addr));
}
__device__ __forceinline__ void ldsm4t(uint32_t* r, uint32_t addr) {
    asm volatile("ldmatrix.sync.aligned.m8n8.x4.trans.shared.b16 {%0,%1,%2,%3}, [%4];"
                 : "=r"(r[0]), "=r"(r[1]), "=r"(r[2]), "=r"(r[3]) : "r"(addr));
}
__device__ __forceinline__ void mma16816(float* d, const uint32_t* a,
                                         const uint32_t* b) {
    asm("mma.sync.aligned.m16n8k16.row.col.f32.f16.f16.f32 "
        "{%0,%1,%2,%3}, {%4,%5,%6,%7}, {%8,%9}, {%0,%1,%2,%3};"
        : "+f"(d[0]), "+f"(d[1]), "+f"(d[2]), "+f"(d[3])
        : "r"(a[0]), "r"(a[1]), "r"(a[2]), "r"(a[3]),
          "r"(b[0]), "r"(b[1]));
}
// pack (v0,v1) into fp16x2 hi + fp16x2 lo-residual
__device__ __forceinline__ void pack_hl(float v0, float v1,
                                        uint32_t& hi, uint32_t& lo) {
    __half2 h = __floats2half2_rn(v0, v1);
    float2 f = __half22float2(h);
    __half2 l = __floats2half2_rn(v0 - f.x, v1 - f.y);
    hi = *(uint32_t*)&h;
    lo = *(uint32_t*)&l;
}

// ================= mma.sync GEMM ============================================
// C[M,N] = A[M,K] @ B^T (B stored [N,K] K-major) + bias.
// TERMS==3: (Ah+Al)@(Bh+Bl) minus ll  (fp32-accurate)
// TERMS==2: (Ah+Al)@Bh                (drops Ah@Bl, ~1.4e-4 rms rel)
#define G_STAGE3  65536            // Ah 16K | Al 16K | Bh 16K | Bl 16K
#define G_STAGE2  49152            // Ah 16K | Al 16K | Bh 16K
#define G_SMEM3   (2*G_STAGE3)
#define G_SMEM2   (2*G_STAGE2)

template<int ACT, int SPLITOUT, int TERMS>
__global__ __launch_bounds__(256)
void gemm_mma(const __half* __restrict__ Ah,
              const __half* __restrict__ Al,
              const __half* __restrict__ Bh,
              const __half* __restrict__ Bl,
              const float* __restrict__ bias,
              float* __restrict__ C,
              __half* __restrict__ Ch,
              __half* __restrict__ Cl,
              int N, int K)
{
    const int STAGE = (TERMS == 3) ? G_STAGE3 : G_STAGE2;
    extern __shared__ __align__(128) char smem[];
    const uint32_t sb = smem_u32(smem);
    const int tid  = threadIdx.x;
    const int wid  = tid >> 5;
    const int lane = tid & 31;
    const int wm   = wid & 3;
    const int wn   = wid >> 2;
    const int bc = blockIdx.x, br = blockIdx.y;

    const __half* Ah_t = Ah + (size_t)br * 128 * K;
    const __half* Al_t = Al + (size_t)br * 128 * K;
    const __half* Bh_t = Bh + (size_t)bc * 128 * K;
    const __half* Bl_t = (TERMS == 3) ? Bl + (size_t)bc * 128 * K : nullptr;
    const int NT = K >> 6;

    auto load_stage = [&](int kt, int s) {
        const uint32_t base = sb + s * STAGE;
        const int koff = kt * 64;
        #pragma unroll
        for (int t = 0; t < 4; t++) {
            int idx = t * 256 + tid;
            int row = idx >> 3, ch = idx & 7;
            uint32_t so = sw128((uint32_t)(row * 128 + ch * 16));
            size_t go = (size_t)row * K + koff + ch * 8;
            cp16(base +         so, Ah_t + go);
            cp16(base + 16384 + so, Al_t + go);
            cp16(base + 32768 + so, Bh_t + go);
            if (TERMS == 3) cp16(base + 49152 + so, Bl_t + go);
        }
        CP_COMMIT();
    };

    float acc[2][8][4];
    #pragma unroll
    for (int mi = 0; mi < 2; mi++)
        #pragma unroll
        for (int nj = 0; nj < 8; nj++)
            #pragma unroll
            for (int e = 0; e < 4; e++) acc[mi][nj][e] = 0.f;

    const int g = lane >> 3, r = lane & 7;

    load_stage(0, 0);

    for (int kt = 0; kt < NT; kt++) {
        const int buf = kt & 1;
        if (kt + 1 < NT) { load_stage(kt + 1, buf ^ 1); CP_WAIT1(); }
        else             { CP_WAIT0(); }
        __syncthreads();

        const uint32_t sA  = sb + buf * STAGE;
        const uint32_t sAl = sA + 16384;
        const uint32_t sBh = sA + 32768;
        const uint32_t sBl = sA + 49152;

        #pragma unroll
        for (int kc = 0; kc < 4; kc++) {
            uint32_t a_h[2][4], a_l[2][4];
            #pragma unroll
            for (int mi = 0; mi < 2; mi++) {
                int arow = wm * 32 + mi * 16 + r + ((g & 1) << 3);
                uint32_t off = sw128((uint32_t)(arow * 128 + kc * 32 +
                                                ((g >> 1) << 4)));
                ldsm4(a_h[mi], sA  + off);
                ldsm4(a_l[mi], sAl + off);
            }
            uint32_t b_h[4][4];
            #pragma unroll
            for (int np = 0; np < 4; np++) {
                int brow = wn * 64 + np * 16 + r + ((g >> 1) << 3);
                uint32_t off = sw128((uint32_t)(brow * 128 + kc * 32 +
                                                ((g & 1) << 4)));
                ldsm4(b_h[np], sBh + off);
            }
            // term 1: hh
            #pragma unroll
            for (int np = 0; np < 4; np++)
                #pragma unroll
                for (int t = 0; t < 2; t++)
                    #pragma unroll
                    for (int mi = 0; mi < 2; mi++)
                        mma16816(acc[mi][np * 2 + t], a_h[mi], &b_h[np][2 * t]);
            // term 2: lh
            #pragma unroll
            for (int np = 0; np < 4; np++)
                #pragma unroll
                for (int t = 0; t < 2; t++)
                    #pragma unroll
                    for (int mi = 0; mi < 2; mi++)
                        mma16816(acc[mi][np * 2 + t], a_l[mi], &b_h[np][2 * t]);
            // term 3: hl (only for TERMS==3)
            if (TERMS == 3) {
                uint32_t b_l[4][4];
                #pragma unroll
                for (int np = 0; np < 4; np++) {
                    int brow = wn * 64 + np * 16 + r + ((g >> 1) << 3);
                    uint32_t off = sw128((uint32_t)(brow * 128 + kc * 32 +
                                                    ((g & 1) << 4)));
                    ldsm4(b_l[np], sBl + off);
                }
                #pragma unroll
                for (int np = 0; np < 4; np++)
                    #pragma unroll
                    for (int t = 0; t < 2; t++)
                        #pragma unroll
                        for (int mi = 0; mi < 2; mi++)
                            mma16816(acc[mi][np * 2 + t], a_h[mi], &b_l[np][2 * t]);
            }
        }
        __syncthreads();
    }

    const int cbase = bc * 128 + wn * 64 + (lane & 3) * 2;
    const int rbase = br * 128 + wm * 32 + (lane >> 2);
    #pragma unroll
    for (int mi = 0; mi < 2; mi++) {
        #pragma unroll
        for (int nj = 0; nj < 8; nj++) {
            int c = cbase + nj * 8;
            float2 bv = *(const float2*)(bias + c);
            float v0 = acc[mi][nj][0] + bv.x;
            float v1 = acc[mi][nj][1] + bv.y;
            float v2 = acc[mi][nj][2] + bv.x;
            float v3 = acc[mi][nj][3] + bv.y;
            if (ACT) {
                v0 = fmaxf(v0, 0.f); v1 = fmaxf(v1, 0.f);
                v2 = fmaxf(v2, 0.f); v3 = fmaxf(v3, 0.f);
            }
            size_t i0 = (size_t)(rbase + mi * 16)     * N + c;
            size_t i1 = (size_t)(rbase + mi * 16 + 8) * N + c;
            if (SPLITOUT) {
                uint32_t h0, l0, h1, l1;
                pack_hl(v0, v1, h0, l0);
                pack_hl(v2, v3, h1, l1);
                *(uint32_t*)(Ch + i0) = h0;
                *(uint32_t*)(Ch + i1) = h1;
                *(uint32_t*)(Cl + i0) = l0;
                *(uint32_t*)(Cl + i1) = l1;
            } else {
                float2 o0; o0.x = v0; o0.y = v1;
                float2 o1; o1.x = v2; o1.y = v3;
                *(float2*)(C + i0) = o0;
                *(float2*)(C + i1) = o1;
            }
        }
    }
}

// ================= Flash attention on tensor cores (fp16, 3-term) ==========
#define A_QH   0
#define A_QL   16384
#define A_ST   32768            // 2 stages x (Kh 8K | Kl 8K | Vh 8K | Vl 8K)
#define A_MK   98304            // 2 x 256 B mask
#define A_SMEM (98304 + 512)

__global__ __launch_bounds__(256)
void attn_mma(const __half* __restrict__ qh,
              const __half* __restrict__ ql,
              const __half* __restrict__ kh,
              const __half* __restrict__ kl,
              const __half* __restrict__ vh,
              const __half* __restrict__ vl,
              const float* __restrict__ mask,
              __half* __restrict__ ch,
              __half* __restrict__ cl)
{
    extern __shared__ __align__(128) char smem[];
    const uint32_t sb = smem_u32(smem);
    const int tid  = threadIdx.x;
    const int wid  = tid >> 5;
    const int lane = tid & 31;
    const int g    = lane >> 3, r8 = lane & 7;
    const int c2   = (lane & 3) * 2;

    const int qt = blockIdx.x;              // 0..7
    const int bh = blockIdx.y;              // 0..127
    const int b  = bh >> 4;
    const int h  = bh & 15;

    const size_t qrow0 = (size_t)b * SS + (size_t)qt * 128;
    const __half* qhg = qh + qrow0 * DD + h * DHH;
    const __half* qlg = ql + qrow0 * DD + h * DHH;
    const __half* khg = kh + (size_t)b * SS * DD + h * DHH;
    const __half* klg = kl + (size_t)b * SS * DD + h * DHH;
    const __half* vhg = vh + (size_t)b * SS * DD + h * DHH;
    const __half* vlg = vl + (size_t)b * SS * DD + h * DHH;
    const float* mkg = mask + (size_t)b * SS;

    auto load_kv = [&](int t, int s) {
        const uint32_t base = sb + A_ST + s * 32768;
        const size_t koff = (size_t)(t * 64) * DD;
        #pragma unroll
        for (int it = 0; it < 8; it++) {
            int idx = it * 256 + tid;
            int mat = idx >> 9;
            int sub = idx & 511;
            int row = sub >> 3, chk = sub & 7;
            uint32_t so = sw128((uint32_t)(row * 128 + chk * 16));
            size_t go = koff + (size_t)row * DD + chk * 8;
            const __half* src =
                (mat == 0) ? khg : (mat == 1) ? klg : (mat == 2) ? vhg : vlg;
            cp16(base + mat * 8192 + so, src + go);
        }
        if (tid < 16)
            cp16(sb + A_MK + s * 256 + tid * 16, mkg + t * 64 + tid * 4);
        CP_COMMIT();
    };

    // Q tile load (with stage 0)
    #pragma unroll
    for (int it = 0; it < 8; it++) {
        int idx = it * 256 + tid;
        int mat = idx >> 10;
        int sub = idx & 1023;
        int row = sub >> 3, chk = sub & 7;
        uint32_t so = sw128((uint32_t)(row * 128 + chk * 16));
        size_t go = (size_t)row * DD + chk * 8;
        cp16(sb + (mat ? A_QL : A_QH) + so, (mat ? qlg : qhg) + go);
    }
    load_kv(0, 0);

    float mA = -INFINITY, mB = -INFINITY, lA = 0.f, lB = 0.f;
    float O[8][4];
    #pragma unroll
    for (int j = 0; j < 8; j++)
        #pragma unroll
        for (int e = 0; e < 4; e++) O[j][e] = 0.f;

    #pragma unroll 1
    for (int t = 0; t < 16; t++) {
        const int buf = t & 1;
        if (t + 1 < 16) { load_kv(t + 1, buf ^ 1); CP_WAIT1(); }
        else            { CP_WAIT0(); }
        __syncthreads();

        const uint32_t sKh = sb + A_ST + buf * 32768;
        const uint32_t sKl = sKh + 8192;
        const uint32_t sVh = sKh + 16384;
        const uint32_t sVl = sKh + 24576;
        const float* mkv = (const float*)(smem + A_MK + buf * 256);

        // ---- S = Q @ K^T (3-term, term-major) ----
        float s_[8][4];
        #pragma unroll
        for (int j = 0; j < 8; j++)
            #pragma unroll
            for (int e = 0; e < 4; e++) s_[j][e] = 0.f;

        #pragma unroll
        for (int kc = 0; kc < 4; kc++) {
            uint32_t aqh[4], aql[4];
            {
                int arow = wid * 16 + r8 + ((g & 1) << 3);
                uint32_t off = sw128((uint32_t)(arow * 128 + kc * 32 +
                                                ((g >> 1) << 4)));
                ldsm4(aqh, sb + A_QH + off);
                ldsm4(aql, sb + A_QL + off);
            }
            uint32_t bkh[4][4], bkl[4][4];
            #pragma unroll
            for (int np = 0; np < 4; np++) {
                int brow = np * 16 + r8 + ((g >> 1) << 3);
                uint32_t off = sw128((uint32_t)(brow * 128 + kc * 32 +
                                                ((g & 1) << 4)));
                ldsm4(bkh[np], sKh + off);
                ldsm4(bkl[np], sKl + off);
            }
            #pragma unroll
            for (int np = 0; np < 4; np++)
                #pragma unroll
                for (int t2 = 0; t2 < 2; t2++)
                    mma16816(s_[np * 2 + t2], aqh, &bkh[np][2 * t2]);
            #pragma unroll
            for (int np = 0; np < 4; np++)
                #pragma unroll
                for (int t2 = 0; t2 < 2; t2++)
                    mma16816(s_[np * 2 + t2], aql, &bkh[np][2 * t2]);
            #pragma unroll
            for (int np = 0; np < 4; np++)
                #pragma unroll
                for (int t2 = 0; t2 < 2; t2++)
                    mma16816(s_[np * 2 + t2], aqh, &bkl[np][2 * t2]);
        }

        // ---- scale + mask, row max ----
        float tmA = -INFINITY, tmB = -INFINITY;
        #pragma unroll
        for (int j = 0; j < 8; j++) {
            float mk0 = mkv[j * 8 + c2]     * (-1e9f);
            float mk1 = mkv[j * 8 + c2 + 1] * (-1e9f);
            s_[j][0] = s_[j][0] * 0.125f + mk0;
            s_[j][1] = s_[j][1] * 0.125f + mk1;
            s_[j][2] = s_[j][2] * 0.125f + mk0;
            s_[j][3] = s_[j][3] * 0.125f + mk1;
            tmA = fmaxf(tmA, fmaxf(s_[j][0], s_[j][1]));
            tmB = fmaxf(tmB, fmaxf(s_[j][2], s_[j][3]));
        }
        tmA = fmaxf(tmA, __shfl_xor_sync(0xffffffffu, tmA, 1));
        tmA = fmaxf(tmA, __shfl_xor_sync(0xffffffffu, tmA, 2));
        tmB = fmaxf(tmB, __shfl_xor_sync(0xffffffffu, tmB, 1));
        tmB = fmaxf(tmB, __shfl_xor_sync(0xffffffffu, tmB, 2));

        const float nmA = fmaxf(mA, tmA), nmB = fmaxf(mB, tmB);
        const float fA = __expf(mA - nmA), fB = __expf(mB - nmB);

        // ---- p = exp(s - m), row sum ----
        float sumA = 0.f, sumB = 0.f;
        #pragma unroll
        for (int j = 0; j < 8; j++) {
            s_[j][0] = __expf(s_[j][0] - nmA);
            s_[j][1] = __expf(s_[j][1] - nmA);
            s_[j][2] = __expf(s_[j][2] - nmB);
            s_[j][3] = __expf(s_[j][3] - nmB);
            sumA += s_[j][0] + s_[j][1];
            sumB += s_[j][2] + s_[j][3];
        }
        sumA += __shfl_xor_sync(0xffffffffu, sumA, 1);
        sumA += __shfl_xor_sync(0xffffffffu, sumA, 2);
        sumB += __shfl_xor_sync(0xffffffffu, sumB, 1);
        sumB += __shfl_xor_sync(0xffffffffu, sumB, 2);
        lA = lA * fA + sumA;  mA = nmA;
        lB = lB * fB + sumB;  mB = nmB;

        // ---- rescale O ----
        #pragma unroll
        for (int j = 0; j < 8; j++) {
            O[j][0] *= fA; O[j][1] *= fA;
            O[j][2] *= fB; O[j][3] *= fB;
        }

        // ---- O += P @ V (3-term, term-major) ----
        #pragma unroll
        for (int c = 0; c < 4; c++) {
            uint32_t ap_h[4], ap_l[4];
            pack_hl(s_[2 * c][0],     s_[2 * c][1],     ap_h[0], ap_l[0]);
            pack_hl(s_[2 * c][2],     s_[2 * c][3],     ap_h[1], ap_l[1]);
            pack_hl(s_[2 * c + 1][0], s_[2 * c + 1][1], ap_h[2], ap_l[2]);
            pack_hl(s_[2 * c + 1][2], s_[2 * c + 1][3], ap_h[3], ap_l[3]);
            uint32_t bvh[4][4], bvl[4][4];
            #pragma unroll
            for (int np2 = 0; np2 < 4; np2++) {
                int vrow = c * 16 + r8 + ((g & 1) << 3);
                uint32_t off = sw128((uint32_t)(vrow * 128 + np2 * 32 +
                                                ((g >> 1) << 4)));
                ldsm4t(bvh[np2], sVh + off);
                ldsm4t(bvl[np2], sVl + off);
            }
            #pragma unroll
            for (int np2 = 0; np2 < 4; np2++)
                #pragma unroll
                for (int t2 = 0; t2 < 2; t2++)
                    mma16816(O[np2 * 2 + t2], ap_h, &bvh[np2][2 * t2]);
            #pragma unroll
            for (int np2 = 0; np2 < 4; np2++)
                #pragma unroll
                for (int t2 = 0; t2 < 2; t2++)
                    mma16816(O[np2 * 2 + t2], ap_l, &bvh[np2][2 * t2]);
            #pragma unroll
            for (int np2 = 0; np2 < 4; np2++)
                #pragma unroll
                for (int t2 = 0; t2 < 2; t2++)
                    mma16816(O[np2 * 2 + t2], ap_h, &bvl[np2][2 * t2]);
        }
        __syncthreads();
    }

    // ---- normalize, split, write ctx ----
    const float liA = 1.f / lA, liB = 1.f / lB;
    const size_t rowA = qrow0 + wid * 16 + (lane >> 2);
    const size_t rowB = rowA + 8;
    const int    colb = h * DHH + c2;
    #pragma unroll
    for (int j = 0; j < 8; j++) {
        uint32_t hi, lo;
        pack_hl(O[j][0] * liA, O[j][1] * liA, hi, lo);
        *(uint32_t*)(ch + rowA * DD + colb + j * 8) = hi;
        *(uint32_t*)(cl + rowA * DD + colb + j * 8) = lo;
        pack_hl(O[j][2] * liB, O[j][3] * liB, hi, lo);
        *(uint32_t*)(ch + rowB * DD + colb + j * 8) = hi;
        *(uint32_t*)(cl + rowB * DD + colb + j * 8) = lo;
    }
}

// ================= fp32 -> fp16 hi/lo split =================================
__global__ __launch_bounds__(256) void split_kernel(
    const float4* __restrict__ in, __half2* __restrict__ oh,
    __half2* __restrict__ ol, int n4)
{
    int i = blockIdx.x * 256 + threadIdx.x;
    if (i >= n4) return;
    float4 v = in[i];
    uint32_t h0, l0, h1, l1;
    pack_hl(v.x, v.y, h0, l0);
    pack_hl(v.z, v.w, h1, l1);
    oh[2 * i]     = *(__half2*)&h0;
    oh[2 * i + 1] = *(__half2*)&h1;
    ol[2 * i]     = *(__half2*)&l0;
    ol[2 * i + 1] = *(__half2*)&l1;
}

// W[K,N] fp32 -> hi(/lo) fp16 [N,K] (transpose + split)
__global__ __launch_bounds__(256) void split_tr_kernel(
    const float* __restrict__ W, __half* __restrict__ oh,
    __half* __restrict__ ol, int K, int N, int want_lo)
{
    __shared__ float t[32][33];
    const int bx = blockIdx.x, by = blockIdx.y;
    const int tx = threadIdx.x, ty = threadIdx.y;   // 32 x 8
    #pragma unroll
    for (int i = 0; i < 4; i++) {
        int rr = ty + i * 8;
        t[rr][tx] = W[(size_t)(by * 32 + rr) * N + bx * 32 + tx];
    }
    __syncthreads();
    #pragma unroll
    for (int i = 0; i < 4; i++) {
        int rr = ty + i * 8;
        float v = t[tx][rr];
        __half h = __float2half_rn(v);
        size_t o = (size_t)(bx * 32 + rr) * K + by * 32 + tx;
        oh[o] = h;
        if (want_lo)
            ol[o] = __float2half_rn(v - __half2float(h));
    }
}

// ================= residual + LayerNorm (optional fused fp16 split) ========
template<int SPL>
__global__ __launch_bounds__(256) void residual_ln_kernel(
    const float* __restrict__ X, const float* __restrict__ Y,
    const float* __restrict__ g, const float* __restrict__ beta,
    float* __restrict__ out,
    __half* __restrict__ oh, __half* __restrict__ ol)
{
    __shared__ float ws[8], ws2[8];
    const int row = blockIdx.x;
    const int tid = threadIdx.x;
    const int lane = tid & 31, warp = tid >> 5;
    const float* px = X + (size_t)row * DD;
    const float* py = Y + (size_t)row * DD;

    float v[4];
    float s = 0.f, s2 = 0.f;
    #pragma unroll
    for (int l = 0; l < 4; l++) {
        int c = tid + l * 256;
        float t = px[c] + py[c];
        v[l] = t; s += t; s2 += t * t;
    }
    #pragma unroll
    for (int off = 16; off; off >>= 1) {
        s  += __shfl_xor_sync(0xffffffffu, s,  off);
        s2 += __shfl_xor_sync(0xffffffffu, s2, off);
    }
    if (lane == 0) { ws[warp] = s; ws2[warp] = s2; }
    __syncthreads();
    if (warp == 0) {
        s  = (lane < 8) ? ws[lane]  : 0.f;
        s2 = (lane < 8) ? ws2[lane] : 0.f;
        #pragma unroll
        for (int off = 4; off; off >>= 1) {
            s  += __shfl_xor_sync(0xffffffffu, s,  off);
            s2 += __shfl_xor_sync(0xffffffffu, s2, off);
        }
        if (lane == 0) { ws[0] = s; ws2[0] = s2; }
    }
    __syncthreads();
    float mu  = ws[0] * (1.f / 1024.f);
    float var = fmaxf(ws2[0] * (1.f / 1024.f) - mu * mu, 0.f);
    float rstd = rsqrtf(var + 1e-6f);
    #pragma unroll
    for (int l = 0; l < 4; l++) {
        int c = tid + l * 256;
        float rv = g[c] * (v[l] - mu) * rstd + beta[c];
        out[(size_t)row * DD + c] = rv;
        if (SPL) {
            __half h = __float2half_rn(rv);
            oh[(size_t)row * DD + c] = h;
            ol[(size_t)row * DD + c] =
                __float2half_rn(rv - __half2float(h));
        }
    }
}

// ================= launch ===================================================
extern "C" void kernel_launch(void* const* d_in, const int* in_sizes, int n_in,
                              void* d_out, int out_size)
{
    const float* x    = (const float*)d_in[0];
    const float* mask = (const float*)d_in[1];
    const float* Wq   = (const float*)d_in[2];
    const float* bq   = (const float*)d_in[3];
    const float* Wk   = (const float*)d_in[4];
    const float* bk   = (const float*)d_in[5];
    const float* Wv   = (const float*)d_in[6];
    const float* bv   = (const float*)d_in[7];
    const float* Wo   = (const float*)d_in[8];
    const float* bo   = (const float*)d_in[9];
    const float* g1   = (const float*)d_in[10];
    const float* be1  = (const float*)d_in[11];
    const float* W1   = (const float*)d_in[12];
    const float* bf1  = (const float*)d_in[13];
    const float* W2   = (const float*)d_in[14];
    const float* bf2  = (const float*)d_in[15];
    const float* g2   = (const float*)d_in[16];
    const float* be2  = (const float*)d_in[17];
    float* out = (float*)d_out;

    float *t1, *x1;
    __half *ah, *al, *qh, *ql, *kh, *kl, *vh, *vl, *hh, *hl;
    __half *wqh, *wql, *wkh, *wkl, *wvh, *wvl, *woh, *wol, *w1h, *w2h;
    cudaGetSymbolAddress((void**)&t1,  g_t1);
    cudaGetSymbolAddress((void**)&x1,  g_x1);
    cudaGetSymbolAddress((void**)&ah,  g_ah);
    cudaGetSymbolAddress((void**)&al,  g_al);
    cudaGetSymbolAddress((void**)&qh,  g_qh);
    cudaGetSymbolAddress((void**)&ql,  g_ql);
    cudaGetSymbolAddress((void**)&kh,  g_kh);
    cudaGetSymbolAddress((void**)&kl,  g_kl);
    cudaGetSymbolAddress((void**)&vh,  g_vh);
    cudaGetSymbolAddress((void**)&vl,  g_vl);
    cudaGetSymbolAddress((void**)&hh,  g_hh);
    cudaGetSymbolAddress((void**)&hl,  g_hl);
    cudaGetSymbolAddress((void**)&wqh, g_wqh);
    cudaGetSymbolAddress((void**)&wql, g_wql);
    cudaGetSymbolAddress((void**)&wkh, g_wkh);
    cudaGetSymbolAddress((void**)&wkl, g_wkl);
    cudaGetSymbolAddress((void**)&wvh, g_wvh);
    cudaGetSymbolAddress((void**)&wvl, g_wvl);
    cudaGetSymbolAddress((void**)&woh, g_woh);
    cudaGetSymbolAddress((void**)&wol, g_wol);
    cudaGetSymbolAddress((void**)&w1h, g_w1h);
    cudaGetSymbolAddress((void**)&w2h, g_w2h);

    cudaFuncSetAttribute(attn_mma,
                         cudaFuncAttributeMaxDynamicSharedMemorySize, A_SMEM);
    cudaFuncSetAttribute(gemm_mma<0, 1, 3>,
                         cudaFuncAttributeMaxDynamicSharedMemorySize, G_SMEM3);
    cudaFuncSetAttribute(gemm_mma<0, 0, 3>,
                         cudaFuncAttributeMaxDynamicSharedMemorySize, G_SMEM3);
    cudaFuncSetAttribute(gemm_mma<1, 1, 2>,
                         cudaFuncAttributeMaxDynamicSharedMemorySize, G_SMEM2);
    cudaFuncSetAttribute(gemm_mma<0, 0, 2>,
                         cudaFuncAttributeMaxDynamicSharedMemorySize, G_SMEM2);

    // lazily-created side stream + events (host-side resources; no device mem)
    static cudaStream_t s2 = nullptr;
    static cudaEvent_t evF, evQ, evK, evV, evO, ev1, ev2;
    if (!s2) {
        cudaStreamCreateWithFlags(&s2, cudaStreamNonBlocking);
        cudaEventCreateWithFlags(&evF, cudaEventDisableTiming);
        cudaEventCreateWithFlags(&evQ, cudaEventDisableTiming);
        cudaEventCreateWithFlags(&evK, cudaEventDisableTiming);
        cudaEventCreateWithFlags(&evV, cudaEventDisableTiming);
        cudaEventCreateWithFlags(&evO, cudaEventDisableTiming);
        cudaEventCreateWithFlags(&ev1, cudaEventDisableTiming);
        cudaEventCreateWithFlags(&ev2, cudaEventDisableTiming);
    }

    const dim3 trDD(DD / 32, DD / 32);
    const dim3 trDF(FF / 32, DD / 32);   // W1: K=DD, N=FF
    const dim3 trFD(DD / 32, FF / 32);   // W2: K=FF, N=DD
    const dim3 tb(32, 8);
    const dim3 gD(DD / 128, MR / 128);   // (8, 64)
    const dim3 gF(FF / 128, MR / 128);   // (32, 64)

    // ---- fork: weight prep on side stream ----
    cudaEventRecord(evF, 0);
    cudaStreamWaitEvent(s2, evF, 0);
    split_tr_kernel<<<trDD, tb, 0, s2>>>(Wq, wqh, wql, DD, DD, 1);
    cudaEventRecord(evQ, s2);
    split_tr_kernel<<<trDD, tb, 0, s2>>>(Wk, wkh, wkl, DD, DD, 1);
    cudaEventRecord(evK, s2);
    split_tr_kernel<<<trDD, tb, 0, s2>>>(Wv, wvh, wvl, DD, DD, 1);
    cudaEventRecord(evV, s2);
    split_tr_kernel<<<trDD, tb, 0, s2>>>(Wo, woh, wol, DD, DD, 1);
    cudaEventRecord(evO, s2);
    split_tr_kernel<<<trDF, tb, 0, s2>>>(W1, w1h, nullptr, DD, FF, 0);
    cudaEventRecord(ev1, s2);
    split_tr_kernel<<<trFD, tb, 0, s2>>>(W2, w2h, nullptr, FF, DD, 0);
    cudaEventRecord(ev2, s2);

    // ---- main stream ----
    split_kernel<<<(MR * DD / 4 + 255) / 256, 256>>>(
        (const float4*)x, (__half2*)ah, (__half2*)al, MR * DD / 4);

    cudaStreamWaitEvent(0, evQ, 0);
    gemm_mma<0, 1, 3><<<gD, 256, G_SMEM3>>>(ah, al, wqh, wql, bq,
                                            nullptr, qh, ql, DD, DD);
    cudaStreamWaitEvent(0, evK, 0);
    gemm_mma<0, 1, 3><<<gD, 256, G_SMEM3>>>(ah, al, wkh, wkl, bk,
                                            nullptr, kh, kl, DD, DD);
    cudaStreamWaitEvent(0, evV, 0);
    gemm_mma<0, 1, 3><<<gD, 256, G_SMEM3>>>(ah, al, wvh, wvl, bv,
                                            nullptr, vh, vl, DD, DD);

    // fused tensor-core attention -> split ctx into ah/al
    attn_mma<<<dim3(8, 128), 256, A_SMEM>>>(qh, ql, kh, kl, vh, vl, mask, ah, al);

    // output projection + residual LN (LN emits split x1 for FFN1)
    cudaStreamWaitEvent(0, evO, 0);
    gemm_mma<0, 0, 3><<<gD, 256, G_SMEM3>>>(ah, al, woh, wol, bo,
                                            t1, nullptr, nullptr, DD, DD);
    residual_ln_kernel<1><<<MR, 256>>>(x, t1, g1, be1, x1, ah, al);

    // FFN1 (2-term): relu(x1 @ W1 + bf1), epilogue writes split fp16 hidden
    cudaStreamWaitEvent(0, ev1, 0);
    gemm_mma<1, 1, 2><<<gF, 256, G_SMEM2>>>(ah, al, w1h, nullptr, bf1,
                                            nullptr, hh, hl, FF, DD);

    // FFN2 (2-term) + residual LN
    cudaStreamWaitEvent(0, ev2, 0);
    gemm_mma<0, 0, 2><<<gD, 256, G_SMEM2>>>(hh, hl, w2h, nullptr, bf2,
                                            t1, nullptr, nullptr, DD, FF);
    residual_ln_kernel<0><<<MR, 256>>>(x1, t1, g2, be2, out, nullptr, nullptr);
}

// round 7
// speedup vs baseline: 1.5016x; 1.2536x over previous
#include <cuda_runtime.h>
#include <cuda_fp16.h>
#include <math.h>
#include <stddef.h>
#include <stdint.h>

#define BB   8
#define SS   1024
#define DD   1024
#define HH   16
#define DHH  64
#define FF   4096
#define MR   (BB*SS)   // 8192 rows

// ---------------- scratch (device globals) ----------------------------------
__device__ float g_t1 [MR*DD];
__device__ float g_x1 [MR*DD];

__device__ __half g_ah[MR*DD];            // activation hi (x / ctx / x1)
__device__ __half g_al[MR*DD];            // activation lo
__device__ __half g_qh[MR*DD];
__device__ __half g_ql[MR*DD];
__device__ __half g_kh[MR*DD];            // K: hi only
__device__ __half g_vh[MR*DD];            // V: hi only
__device__ __half g_hh[(size_t)MR*FF];    // FFN hidden hi
__device__ __half g_hl[(size_t)MR*FF];    // FFN hidden lo
// weights: hi only, [N,K] K-major
__device__ __half g_wqh[DD*DD];
__device__ __half g_wkh[DD*DD];
__device__ __half g_wvh[DD*DD];
__device__ __half g_woh[DD*DD];
__device__ __half g_w1h[(size_t)DD*FF];
__device__ __half g_w2h[(size_t)FF*DD];

// ================= PTX helpers ==============================================
__device__ __forceinline__ uint32_t smem_u32(const void* p) {
    uint32_t a;
    asm("{ .reg .u64 t; cvta.to.shared.u64 t, %1; cvt.u32.u64 %0, t; }"
        : "=r"(a) : "l"(p));
    return a;
}
__device__ __forceinline__ uint32_t sw128(uint32_t o) {
    return o ^ ((o >> 3) & 0x70);
}
__device__ __forceinline__ void cp16(uint32_t s, const void* g) {
    asm volatile("cp.async.cg.shared.global [%0], [%1], 16;" :: "r"(s), "l"(g));
}
#define CP_COMMIT()  asm volatile("cp.async.commit_group;" ::: "memory")
#define CP_WAIT0()   asm volatile("cp.async.wait_group 0;" ::: "memory")
#define CP_WAIT1()   asm volatile("cp.async.wait_group 1;" ::: "memory")

__device__ __forceinline__ void ldsm4(uint32_t* r, uint32_t addr) {
    asm volatile("ldmatrix.sync.aligned.m8n8.x4.shared.b16 {%0,%1,%2,%3}, [%4];"
                 : "=r"(r[0]), "=r"(r[1]), "=r"(r[2]), "=r"(r[3]) : "r"(addr));
}
__device__ __forceinline__ void ldsm4t(uint32_t* r, uint32_t addr) {
    asm volatile("ldmatrix.sync.aligned.m8n8.x4.trans.shared.b16 {%0,%1,%2,%3}, [%4];"
                 : "=r"(r[0]), "=r"(r[1]), "=r"(r[2]), "=r"(r[3]) : "r"(addr));
}
__device__ __forceinline__ void mma16816(float* d, const uint32_t* a,
                                         const uint32_t* b) {
    asm("mma.sync.aligned.m16n8k16.row.col.f32.f16.f16.f32 "
        "{%0,%1,%2,%3}, {%4,%5,%6,%7}, {%8,%9}, {%0,%1,%2,%3};"
        : "+f"(d[0]), "+f"(d[1]), "+f"(d[2]), "+f"(d[3])
        : "r"(a[0]), "r"(a[1]), "r"(a[2]), "r"(a[3]),
          "r"(b[0]), "r"(b[1]));
}
__device__ __forceinline__ void pack_hl(float v0, float v1,
                                        uint32_t& hi, uint32_t& lo) {
    __half2 h = __floats2half2_rn(v0, v1);
    float2 f = __half22float2(h);
    __half2 l = __floats2half2_rn(v0 - f.x, v1 - f.y);
    hi = *(uint32_t*)&h;
    lo = *(uint32_t*)&l;
}

// ================= mma.sync GEMM (2-term: (Ah+Al)@Bh) ======================
// SPLITOUT: 0 -> fp32 C,  1 -> fp16 hi+lo,  2 -> fp16 hi only
#define G_STAGE  49152            // Ah 16K | Al 16K | Bh 16K
#define G_SMEM   (2*G_STAGE)      // 96 KB -> 2 CTAs/SM

template<int ACT, int SPLITOUT>
__global__ __launch_bounds__(256, 2)
void gemm_mma(const __half* __restrict__ Ah,
              const __half* __restrict__ Al,
              const __half* __restrict__ Bh,
              const float* __restrict__ bias,
              float* __restrict__ C,
              __half* __restrict__ Ch,
              __half* __restrict__ Cl,
              int N, int K)
{
    extern __shared__ __align__(128) char smem[];
    const uint32_t sb = smem_u32(smem);
    const int tid  = threadIdx.x;
    const int wid  = tid >> 5;
    const int lane = tid & 31;
    const int wm   = wid & 3;
    const int wn   = wid >> 2;
    const int bc = blockIdx.x, br = blockIdx.y;

    const __half* Ah_t = Ah + (size_t)br * 128 * K;
    const __half* Al_t = Al + (size_t)br * 128 * K;
    const __half* Bh_t = Bh + (size_t)bc * 128 * K;
    const int NT = K >> 6;

    auto load_stage = [&](int kt, int s) {
        const uint32_t base = sb + s * G_STAGE;
        const int koff = kt * 64;
        #pragma unroll
        for (int t = 0; t < 4; t++) {
            int idx = t * 256 + tid;
            int row = idx >> 3, ch = idx & 7;
            uint32_t so = sw128((uint32_t)(row * 128 + ch * 16));
            size_t go = (size_t)row * K + koff + ch * 8;
            cp16(base +         so, Ah_t + go);
            cp16(base + 16384 + so, Al_t + go);
            cp16(base + 32768 + so, Bh_t + go);
        }
        CP_COMMIT();
    };

    float acc[2][8][4];
    #pragma unroll
    for (int mi = 0; mi < 2; mi++)
        #pragma unroll
        for (int nj = 0; nj < 8; nj++)
            #pragma unroll
            for (int e = 0; e < 4; e++) acc[mi][nj][e] = 0.f;

    const int g = lane >> 3, r = lane & 7;

    load_stage(0, 0);

    for (int kt = 0; kt < NT; kt++) {
        const int buf = kt & 1;
        if (kt + 1 < NT) { load_stage(kt + 1, buf ^ 1); CP_WAIT1(); }
        else             { CP_WAIT0(); }
        __syncthreads();

        const uint32_t sA  = sb + buf * G_STAGE;
        const uint32_t sAl = sA + 16384;
        const uint32_t sBh = sA + 32768;

        #pragma unroll
        for (int kc = 0; kc < 4; kc++) {
            uint32_t a_h[2][4], a_l[2][4];
            #pragma unroll
            for (int mi = 0; mi < 2; mi++) {
                int arow = wm * 32 + mi * 16 + r + ((g & 1) << 3);
                uint32_t off = sw128((uint32_t)(arow * 128 + kc * 32 +
                                                ((g >> 1) << 4)));
                ldsm4(a_h[mi], sA  + off);
                ldsm4(a_l[mi], sAl + off);
            }
            uint32_t b_h[4][4];
            #pragma unroll
            for (int np = 0; np < 4; np++) {
                int brow = wn * 64 + np * 16 + r + ((g >> 1) << 3);
                uint32_t off = sw128((uint32_t)(brow * 128 + kc * 32 +
                                                ((g & 1) << 4)));
                ldsm4(b_h[np], sBh + off);
            }
            #pragma unroll
            for (int np = 0; np < 4; np++)
                #pragma unroll
                for (int t = 0; t < 2; t++)
                    #pragma unroll
                    for (int mi = 0; mi < 2; mi++)
                        mma16816(acc[mi][np * 2 + t], a_h[mi], &b_h[np][2 * t]);
            #pragma unroll
            for (int np = 0; np < 4; np++)
                #pragma unroll
                for (int t = 0; t < 2; t++)
                    #pragma unroll
                    for (int mi = 0; mi < 2; mi++)
                        mma16816(acc[mi][np * 2 + t], a_l[mi], &b_h[np][2 * t]);
        }
        __syncthreads();
    }

    const int cbase = bc * 128 + wn * 64 + (lane & 3) * 2;
    const int rbase = br * 128 + wm * 32 + (lane >> 2);
    #pragma unroll
    for (int mi = 0; mi < 2; mi++) {
        #pragma unroll
        for (int nj = 0; nj < 8; nj++) {
            int c = cbase + nj * 8;
            float2 bv = *(const float2*)(bias + c);
            float v0 = acc[mi][nj][0] + bv.x;
            float v1 = acc[mi][nj][1] + bv.y;
            float v2 = acc[mi][nj][2] + bv.x;
            float v3 = acc[mi][nj][3] + bv.y;
            if (ACT) {
                v0 = fmaxf(v0, 0.f); v1 = fmaxf(v1, 0.f);
                v2 = fmaxf(v2, 0.f); v3 = fmaxf(v3, 0.f);
            }
            size_t i0 = (size_t)(rbase + mi * 16)     * N + c;
            size_t i1 = (size_t)(rbase + mi * 16 + 8) * N + c;
            if (SPLITOUT == 1) {
                uint32_t h0, l0, h1, l1;
                pack_hl(v0, v1, h0, l0);
                pack_hl(v2, v3, h1, l1);
                *(uint32_t*)(Ch + i0) = h0;
                *(uint32_t*)(Ch + i1) = h1;
                *(uint32_t*)(Cl + i0) = l0;
                *(uint32_t*)(Cl + i1) = l1;
            } else if (SPLITOUT == 2) {
                __half2 h0 = __floats2half2_rn(v0, v1);
                __half2 h1 = __floats2half2_rn(v2, v3);
                *(__half2*)(Ch + i0) = h0;
                *(__half2*)(Ch + i1) = h1;
            } else {
                float2 o0; o0.x = v0; o0.y = v1;
                float2 o1; o1.x = v2; o1.y = v3;
                *(float2*)(C + i0) = o0;
                *(float2*)(C + i1) = o1;
            }
        }
    }
}

// ================= Flash attention (fp16 2-term, 2 CTAs/SM) =================
#define A_QH   0
#define A_QL   16384
#define A_ST   32768            // 2 stages x (Kh 8K | Vh 8K)
#define A_MK   65536            // 2 x 256 B mask
#define A_SMEM (65536 + 512)

__global__ __launch_bounds__(256, 2)
void attn_mma(const __half* __restrict__ qh,
              const __half* __restrict__ ql,
              const __half* __restrict__ kh,
              const __half* __restrict__ vh,
              const float* __restrict__ mask,
              __half* __restrict__ ch,
              __half* __restrict__ cl)
{
    extern __shared__ __align__(128) char smem[];
    const uint32_t sb = smem_u32(smem);
    const int tid  = threadIdx.x;
    const int wid  = tid >> 5;
    const int lane = tid & 31;
    const int g    = lane >> 3, r8 = lane & 7;
    const int c2   = (lane & 3) * 2;

    const int qt = blockIdx.x;              // 0..7
    const int bh = blockIdx.y;              // 0..127
    const int b  = bh >> 4;
    const int h  = bh & 15;

    const size_t qrow0 = (size_t)b * SS + (size_t)qt * 128;
    const __half* qhg = qh + qrow0 * DD + h * DHH;
    const __half* qlg = ql + qrow0 * DD + h * DHH;
    const __half* khg = kh + (size_t)b * SS * DD + h * DHH;
    const __half* vhg = vh + (size_t)b * SS * DD + h * DHH;
    const float* mkg = mask + (size_t)b * SS;

    auto load_kv = [&](int t, int s) {
        const uint32_t base = sb + A_ST + s * 16384;
        const size_t koff = (size_t)(t * 64) * DD;
        #pragma unroll
        for (int it = 0; it < 4; it++) {
            int idx = it * 256 + tid;            // 0..1023
            int mat = idx >> 9;                  // 0: Kh, 1: Vh
            int sub = idx & 511;
            int row = sub >> 3, chk = sub & 7;
            uint32_t so = sw128((uint32_t)(row * 128 + chk * 16));
            size_t go = koff + (size_t)row * DD + chk * 8;
            cp16(base + mat * 8192 + so, (mat ? vhg : khg) + go);
        }
        if (tid < 16)
            cp16(sb + A_MK + s * 256 + tid * 16, mkg + t * 64 + tid * 4);
        CP_COMMIT();
    };

    // Q tile load (with stage 0)
    #pragma unroll
    for (int it = 0; it < 8; it++) {
        int idx = it * 256 + tid;                // 0..2047
        int mat = idx >> 10;                     // 0: qh, 1: ql
        int sub = idx & 1023;
        int row = sub >> 3, chk = sub & 7;
        uint32_t so = sw128((uint32_t)(row * 128 + chk * 16));
        size_t go = (size_t)row * DD + chk * 8;
        cp16(sb + (mat ? A_QL : A_QH) + so, (mat ? qlg : qhg) + go);
    }
    load_kv(0, 0);

    float mA = -INFINITY, mB = -INFINITY, lA = 0.f, lB = 0.f;
    float O[8][4];
    #pragma unroll
    for (int j = 0; j < 8; j++)
        #pragma unroll
        for (int e = 0; e < 4; e++) O[j][e] = 0.f;

    #pragma unroll 1
    for (int t = 0; t < 16; t++) {
        const int buf = t & 1;
        if (t + 1 < 16) { load_kv(t + 1, buf ^ 1); CP_WAIT1(); }
        else            { CP_WAIT0(); }
        __syncthreads();

        const uint32_t sKh = sb + A_ST + buf * 16384;
        const uint32_t sVh = sKh + 8192;
        const float* mkv = (const float*)(smem + A_MK + buf * 256);

        // ---- S = Q @ K^T (2-term: qh + ql, against Kh) ----
        float s_[8][4];
        #pragma unroll
        for (int j = 0; j < 8; j++)
            #pragma unroll
            for (int e = 0; e < 4; e++) s_[j][e] = 0.f;

        #pragma unroll
        for (int kc = 0; kc < 4; kc++) {
            uint32_t aqh[4], aql[4];
            {
                int arow = wid * 16 + r8 + ((g & 1) << 3);
                uint32_t off = sw128((uint32_t)(arow * 128 + kc * 32 +
                                                ((g >> 1) << 4)));
                ldsm4(aqh, sb + A_QH + off);
                ldsm4(aql, sb + A_QL + off);
            }
            uint32_t bkh[4][4];
            #pragma unroll
            for (int np = 0; np < 4; np++) {
                int brow = np * 16 + r8 + ((g >> 1) << 3);
                uint32_t off = sw128((uint32_t)(brow * 128 + kc * 32 +
                                                ((g & 1) << 4)));
                ldsm4(bkh[np], sKh + off);
            }
            #pragma unroll
            for (int np = 0; np < 4; np++)
                #pragma unroll
                for (int t2 = 0; t2 < 2; t2++)
                    mma16816(s_[np * 2 + t2], aqh, &bkh[np][2 * t2]);
            #pragma unroll
            for (int np = 0; np < 4; np++)
                #pragma unroll
                for (int t2 = 0; t2 < 2; t2++)
                    mma16816(s_[np * 2 + t2], aql, &bkh[np][2 * t2]);
        }

        // ---- scale + mask, row max ----
        float tmA = -INFINITY, tmB = -INFINITY;
        #pragma unroll
        for (int j = 0; j < 8; j++) {
            float mk0 = mkv[j * 8 + c2]     * (-1e9f);
            float mk1 = mkv[j * 8 + c2 + 1] * (-1e9f);
            s_[j][0] = s_[j][0] * 0.125f + mk0;
            s_[j][1] = s_[j][1] * 0.125f + mk1;
            s_[j][2] = s_[j][2] * 0.125f + mk0;
            s_[j][3] = s_[j][3] * 0.125f + mk1;
            tmA = fmaxf(tmA, fmaxf(s_[j][0], s_[j][1]));
            tmB = fmaxf(tmB, fmaxf(s_[j][2], s_[j][3]));
        }
        tmA = fmaxf(tmA, __shfl_xor_sync(0xffffffffu, tmA, 1));
        tmA = fmaxf(tmA, __shfl_xor_sync(0xffffffffu, tmA, 2));
        tmB = fmaxf(tmB, __shfl_xor_sync(0xffffffffu, tmB, 1));
        tmB = fmaxf(tmB, __shfl_xor_sync(0xffffffffu, tmB, 2));

        const float nmA = fmaxf(mA, tmA), nmB = fmaxf(mB, tmB);
        const float fA = __expf(mA - nmA), fB = __expf(mB - nmB);

        float sumA = 0.f, sumB = 0.f;
        #pragma unroll
        for (int j = 0; j < 8; j++) {
            s_[j][0] = __expf(s_[j][0] - nmA);
            s_[j][1] = __expf(s_[j][1] - nmA);
            s_[j][2] = __expf(s_[j][2] - nmB);
            s_[j][3] = __expf(s_[j][3] - nmB);
            sumA += s_[j][0] + s_[j][1];
            sumB += s_[j][2] + s_[j][3];
        }
        sumA += __shfl_xor_sync(0xffffffffu, sumA, 1);
        sumA += __shfl_xor_sync(0xffffffffu, sumA, 2);
        sumB += __shfl_xor_sync(0xffffffffu, sumB, 1);
        sumB += __shfl_xor_sync(0xffffffffu, sumB, 2);
        lA = lA * fA + sumA;  mA = nmA;
        lB = lB * fB + sumB;  mB = nmB;

        #pragma unroll
        for (int j = 0; j < 8; j++) {
            O[j][0] *= fA; O[j][1] *= fA;
            O[j][2] *= fB; O[j][3] *= fB;
        }

        // ---- O += P @ V (2-term: P hi+lo, against Vh) ----
        #pragma unroll
        for (int c = 0; c < 4; c++) {
            uint32_t ap_h[4], ap_l[4];
            pack_hl(s_[2 * c][0],     s_[2 * c][1],     ap_h[0], ap_l[0]);
            pack_hl(s_[2 * c][2],     s_[2 * c][3],     ap_h[1], ap_l[1]);
            pack_hl(s_[2 * c + 1][0], s_[2 * c + 1][1], ap_h[2], ap_l[2]);
            pack_hl(s_[2 * c + 1][2], s_[2 * c + 1][3], ap_h[3], ap_l[3]);
            uint32_t bvh[4][4];
            #pragma unroll
            for (int np2 = 0; np2 < 4; np2++) {
                int vrow = c * 16 + r8 + ((g & 1) << 3);
                uint32_t off = sw128((uint32_t)(vrow * 128 + np2 * 32 +
                                                ((g >> 1) << 4)));
                ldsm4t(bvh[np2], sVh + off);
            }
            #pragma unroll
            for (int np2 = 0; np2 < 4; np2++)
                #pragma unroll
                for (int t2 = 0; t2 < 2; t2++)
                    mma16816(O[np2 * 2 + t2], ap_h, &bvh[np2][2 * t2]);
            #pragma unroll
            for (int np2 = 0; np2 < 4; np2++)
                #pragma unroll
                for (int t2 = 0; t2 < 2; t2++)
                    mma16816(O[np2 * 2 + t2], ap_l, &bvh[np2][2 * t2]);
        }
        __syncthreads();
    }

    // ---- normalize, split, write ctx ----
    const float liA = 1.f / lA, liB = 1.f / lB;
    const size_t rowA = qrow0 + wid * 16 + (lane >> 2);
    const size_t rowB = rowA + 8;
    const int    colb = h * DHH + c2;
    #pragma unroll
    for (int j = 0; j < 8; j++) {
        uint32_t hi, lo;
        pack_hl(O[j][0] * liA, O[j][1] * liA, hi, lo);
        *(uint32_t*)(ch + rowA * DD + colb + j * 8) = hi;
        *(uint32_t*)(cl + rowA * DD + colb + j * 8) = lo;
        pack_hl(O[j][2] * liB, O[j][3] * liB, hi, lo);
        *(uint32_t*)(ch + rowB * DD + colb + j * 8) = hi;
        *(uint32_t*)(cl + rowB * DD + colb + j * 8) = lo;
    }
}

// ================= fp32 -> fp16 hi/lo split =================================
__global__ __launch_bounds__(256) void split_kernel(
    const float4* __restrict__ in, __half2* __restrict__ oh,
    __half2* __restrict__ ol, int n4)
{
    int i = blockIdx.x * 256 + threadIdx.x;
    if (i >= n4) return;
    float4 v = in[i];
    uint32_t h0, l0, h1, l1;
    pack_hl(v.x, v.y, h0, l0);
    pack_hl(v.z, v.w, h1, l1);
    oh[2 * i]     = *(__half2*)&h0;
    oh[2 * i + 1] = *(__half2*)&h1;
    ol[2 * i]     = *(__half2*)&l0;
    ol[2 * i + 1] = *(__half2*)&l1;
}

// W[K,N] fp32 -> hi fp16 [N,K] (transpose)
__global__ __launch_bounds__(256) void split_tr_kernel(
    const float* __restrict__ W, __half* __restrict__ oh, int K, int N)
{
    __shared__ float t[32][33];
    const int bx = blockIdx.x, by = blockIdx.y;
    const int tx = threadIdx.x, ty = threadIdx.y;   // 32 x 8
    #pragma unroll
    for (int i = 0; i < 4; i++) {
        int rr = ty + i * 8;
        t[rr][tx] = W[(size_t)(by * 32 + rr) * N + bx * 32 + tx];
    }
    __syncthreads();
    #pragma unroll
    for (int i = 0; i < 4; i++) {
        int rr = ty + i * 8;
        size_t o = (size_t)(bx * 32 + rr) * K + by * 32 + tx;
        oh[o] = __float2half_rn(t[tx][rr]);
    }
}

// ================= residual + LayerNorm (optional fused fp16 split) ========
template<int SPL>
__global__ __launch_bounds__(256) void residual_ln_kernel(
    const float* __restrict__ X, const float* __restrict__ Y,
    const float* __restrict__ g, const float* __restrict__ beta,
    float* __restrict__ out,
    __half* __restrict__ oh, __half* __restrict__ ol)
{
    __shared__ float ws[8], ws2[8];
    const int row = blockIdx.x;
    const int tid = threadIdx.x;
    const int lane = tid & 31, warp = tid >> 5;
    const float* px = X + (size_t)row * DD;
    const float* py = Y + (size_t)row * DD;

    float v[4];
    float s = 0.f, s2 = 0.f;
    #pragma unroll
    for (int l = 0; l < 4; l++) {
        int c = tid + l * 256;
        float t = px[c] + py[c];
        v[l] = t; s += t; s2 += t * t;
    }
    #pragma unroll
    for (int off = 16; off; off >>= 1) {
        s  += __shfl_xor_sync(0xffffffffu, s,  off);
        s2 += __shfl_xor_sync(0xffffffffu, s2, off);
    }
    if (lane == 0) { ws[warp] = s; ws2[warp] = s2; }
    __syncthreads();
    if (warp == 0) {
        s  = (lane < 8) ? ws[lane]  : 0.f;
        s2 = (lane < 8) ? ws2[lane] : 0.f;
        #pragma unroll
        for (int off = 4; off; off >>= 1) {
            s  += __shfl_xor_sync(0xffffffffu, s,  off);
            s2 += __shfl_xor_sync(0xffffffffu, s2, off);
        }
        if (lane == 0) { ws[0] = s; ws2[0] = s2; }
    }
    __syncthreads();
    float mu  = ws[0] * (1.f / 1024.f);
    float var = fmaxf(ws2[0] * (1.f / 1024.f) - mu * mu, 0.f);
    float rstd = rsqrtf(var + 1e-6f);
    #pragma unroll
    for (int l = 0; l < 4; l++) {
        int c = tid + l * 256;
        float rv = g[c] * (v[l] - mu) * rstd + beta[c];
        out[(size_t)row * DD + c] = rv;
        if (SPL) {
            __half h = __float2half_rn(rv);
            oh[(size_t)row * DD + c] = h;
            ol[(size_t)row * DD + c] =
                __float2half_rn(rv - __half2float(h));
        }
    }
}

// ================= launch ===================================================
extern "C" void kernel_launch(void* const* d_in, const int* in_sizes, int n_in,
                              void* d_out, int out_size)
{
    const float* x    = (const float*)d_in[0];
    const float* mask = (const float*)d_in[1];
    const float* Wq   = (const float*)d_in[2];
    const float* bq   = (const float*)d_in[3];
    const float* Wk   = (const float*)d_in[4];
    const float* bk   = (const float*)d_in[5];
    const float* Wv   = (const float*)d_in[6];
    const float* bv   = (const float*)d_in[7];
    const float* Wo   = (const float*)d_in[8];
    const float* bo   = (const float*)d_in[9];
    const float* g1   = (const float*)d_in[10];
    const float* be1  = (const float*)d_in[11];
    const float* W1   = (const float*)d_in[12];
    const float* bf1  = (const float*)d_in[13];
    const float* W2   = (const float*)d_in[14];
    const float* bf2  = (const float*)d_in[15];
    const float* g2   = (const float*)d_in[16];
    const float* be2  = (const float*)d_in[17];
    float* out = (float*)d_out;

    float *t1, *x1;
    __half *ah, *al, *qh, *ql, *kh, *vh, *hh, *hl;
    __half *wqh, *wkh, *wvh, *woh, *w1h, *w2h;
    cudaGetSymbolAddress((void**)&t1,  g_t1);
    cudaGetSymbolAddress((void**)&x1,  g_x1);
    cudaGetSymbolAddress((void**)&ah,  g_ah);
    cudaGetSymbolAddress((void**)&al,  g_al);
    cudaGetSymbolAddress((void**)&qh,  g_qh);
    cudaGetSymbolAddress((void**)&ql,  g_ql);
    cudaGetSymbolAddress((void**)&kh,  g_kh);
    cudaGetSymbolAddress((void**)&vh,  g_vh);
    cudaGetSymbolAddress((void**)&hh,  g_hh);
    cudaGetSymbolAddress((void**)&hl,  g_hl);
    cudaGetSymbolAddress((void**)&wqh, g_wqh);
    cudaGetSymbolAddress((void**)&wkh, g_wkh);
    cudaGetSymbolAddress((void**)&wvh, g_wvh);
    cudaGetSymbolAddress((void**)&woh, g_woh);
    cudaGetSymbolAddress((void**)&w1h, g_w1h);
    cudaGetSymbolAddress((void**)&w2h, g_w2h);

    cudaFuncSetAttribute(attn_mma,
                         cudaFuncAttributeMaxDynamicSharedMemorySize, A_SMEM);
    cudaFuncSetAttribute(gemm_mma<0, 0>,
                         cudaFuncAttributeMaxDynamicSharedMemorySize, G_SMEM);
    cudaFuncSetAttribute(gemm_mma<0, 1>,
                         cudaFuncAttributeMaxDynamicSharedMemorySize, G_SMEM);
    cudaFuncSetAttribute(gemm_mma<0, 2>,
                         cudaFuncAttributeMaxDynamicSharedMemorySize, G_SMEM);
    cudaFuncSetAttribute(gemm_mma<1, 1>,
                         cudaFuncAttributeMaxDynamicSharedMemorySize, G_SMEM);

    // lazily-created side streams + events (host-side; no device mem)
    static cudaStream_t s2 = nullptr, s3 = nullptr;
    static cudaEvent_t evF, evX, evK, evQp, evVp, ev1p, evO, ev2;
    if (!s2) {
        cudaStreamCreateWithFlags(&s2, cudaStreamNonBlocking);
        cudaStreamCreateWithFlags(&s3, cudaStreamNonBlocking);
        cudaEventCreateWithFlags(&evF,  cudaEventDisableTiming);
        cudaEventCreateWithFlags(&evX,  cudaEventDisableTiming);
        cudaEventCreateWithFlags(&evK,  cudaEventDisableTiming);
        cudaEventCreateWithFlags(&evQp, cudaEventDisableTiming);
        cudaEventCreateWithFlags(&evVp, cudaEventDisableTiming);
        cudaEventCreateWithFlags(&ev1p, cudaEventDisableTiming);
        cudaEventCreateWithFlags(&evO,  cudaEventDisableTiming);
        cudaEventCreateWithFlags(&ev2,  cudaEventDisableTiming);
    }

    const dim3 trDD(DD / 32, DD / 32);
    const dim3 trDF(FF / 32, DD / 32);   // W1: K=DD, N=FF
    const dim3 trFD(DD / 32, FF / 32);   // W2: K=FF, N=DD
    const dim3 tb(32, 8);
    const dim3 gD(DD / 128, MR / 128);   // (8, 64)
    const dim3 gF(FF / 128, MR / 128);   // (32, 64)

    // ---- fork ----
    cudaEventRecord(evF, 0);
    cudaStreamWaitEvent(s2, evF, 0);
    cudaStreamWaitEvent(s3, evF, 0);

    // s3: preps for Wq, Wv, W1
    split_tr_kernel<<<trDD, tb, 0, s3>>>(Wq, wqh, DD, DD);
    cudaEventRecord(evQp, s3);
    split_tr_kernel<<<trDD, tb, 0, s3>>>(Wv, wvh, DD, DD);
    cudaEventRecord(evVp, s3);
    split_tr_kernel<<<trDF, tb, 0, s3>>>(W1, w1h, DD, FF);
    cudaEventRecord(ev1p, s3);

    // main: x split
    split_kernel<<<(MR * DD / 4 + 255) / 256, 256>>>(
        (const float4*)x, (__half2*)ah, (__half2*)al, MR * DD / 4);
    cudaEventRecord(evX, 0);

    // s2: Wk prep, K GEMM (concurrent with Q/V on main), then Wo/W2 preps
    split_tr_kernel<<<trDD, tb, 0, s2>>>(Wk, wkh, DD, DD);
    cudaStreamWaitEvent(s2, evX, 0);
    gemm_mma<0, 2><<<gD, 256, G_SMEM, s2>>>(ah, al, wkh, bk,
                                            nullptr, kh, nullptr, DD, DD);
    cudaEventRecord(evK, s2);
    split_tr_kernel<<<trDD, tb, 0, s2>>>(Wo, woh, DD, DD);
    cudaEventRecord(evO, s2);
    split_tr_kernel<<<trFD, tb, 0, s2>>>(W2, w2h, FF, DD);
    cudaEventRecord(ev2, s2);

    // main: Q and V projections
    cudaStreamWaitEvent(0, evQp, 0);
    gemm_mma<0, 1><<<gD, 256, G_SMEM>>>(ah, al, wqh, bq,
                                        nullptr, qh, ql, DD, DD);
    cudaStreamWaitEvent(0, evVp, 0);
    gemm_mma<0, 2><<<gD, 256, G_SMEM>>>(ah, al, wvh, bv,
                                        nullptr, vh, nullptr, DD, DD);

    // attention -> split ctx into ah/al
    cudaStreamWaitEvent(0, evK, 0);
    attn_mma<<<dim3(8, 128), 256, A_SMEM>>>(qh, ql, kh, vh, mask, ah, al);

    // output projection + residual LN (LN emits split x1 -> ah/al)
    cudaStreamWaitEvent(0, evO, 0);
    gemm_mma<0, 0><<<gD, 256, G_SMEM>>>(ah, al, woh, bo,
                                        t1, nullptr, nullptr, DD, DD);
    residual_ln_kernel<1><<<MR, 256>>>(x, t1, g1, be1, x1, ah, al);

    // FFN1: relu(x1 @ W1 + bf1) -> split fp16 hidden
    cudaStreamWaitEvent(0, ev1p, 0);
    gemm_mma<1, 1><<<gF, 256, G_SMEM>>>(ah, al, w1h, bf1,
                                        nullptr, hh, hl, FF, DD);

    // FFN2 + residual LN
    cudaStreamWaitEvent(0, ev2, 0);
    gemm_mma<0, 0><<<gD, 256, G_SMEM>>>(hh, hl, w2h, bf2,
                                        t1, nullptr, nullptr, DD, FF);
    residual_ln_kernel<0><<<MR, 256>>>(x1, t1, g2, be2, out, nullptr, nullptr);
}

// round 8
// speedup vs baseline: 2.0055x; 1.3356x over previous
#include <cuda_runtime.h>
#include <cuda_fp16.h>
#include <math.h>
#include <stddef.h>
#include <stdint.h>

#define BB   8
#define SS   1024
#define DD   1024
#define HH   16
#define DHH  64
#define FF   4096
#define MR   (BB*SS)   // 8192 rows

// ---------------- scratch (device globals) ----------------------------------
__device__ float g_t1 [MR*DD];
__device__ float g_x1 [MR*DD];

__device__ __half g_ah[MR*DD];            // activation hi (x / ctx / x1)
__device__ __half g_al[MR*DD];            // activation lo (x / ctx)
__device__ __half g_qh[MR*DD];
__device__ __half g_ql[MR*DD];
__device__ __half g_kh[MR*DD];
__device__ __half g_vh[MR*DD];
__device__ __half g_hh[(size_t)MR*FF];    // FFN hidden (hi only)
// weights, [N,K] K-major, hi only
__device__ __half g_wqkv[3*DD*DD];        // packed Wq|Wk|Wv
__device__ float  g_bqkv[3*DD];           // packed bq|bk|bv
__device__ __half g_woh[DD*DD];
__device__ __half g_w1h[(size_t)DD*FF];
__device__ __half g_w2h[(size_t)FF*DD];

// ================= PTX helpers ==============================================
__device__ __forceinline__ uint32_t smem_u32(const void* p) {
    uint32_t a;
    asm("{ .reg .u64 t; cvta.to.shared.u64 t, %1; cvt.u32.u64 %0, t; }"
        : "=r"(a) : "l"(p));
    return a;
}
__device__ __forceinline__ uint32_t sw128(uint32_t o) {
    return o ^ ((o >> 3) & 0x70);
}
__device__ __forceinline__ void cp16(uint32_t s, const void* g) {
    asm volatile("cp.async.cg.shared.global [%0], [%1], 16;" :: "r"(s), "l"(g));
}
#define CP_COMMIT()  asm volatile("cp.async.commit_group;" ::: "memory")
#define CP_WAIT0()   asm volatile("cp.async.wait_group 0;" ::: "memory")
#define CP_WAIT1()   asm volatile("cp.async.wait_group 1;" ::: "memory")

__device__ __forceinline__ void ldsm4(uint32_t* r, uint32_t addr) {
    asm volatile("ldmatrix.sync.aligned.m8n8.x4.shared.b16 {%0,%1,%2,%3}, [%4];"
                 : "=r"(r[0]), "=r"(r[1]), "=r"(r[2]), "=r"(r[3]) : "r"(addr));
}
__device__ __forceinline__ void ldsm4t(uint32_t* r, uint32_t addr) {
    asm volatile("ldmatrix.sync.aligned.m8n8.x4.trans.shared.b16 {%0,%1,%2,%3}, [%4];"
                 : "=r"(r[0]), "=r"(r[1]), "=r"(r[2]), "=r"(r[3]) : "r"(addr));
}
__device__ __forceinline__ void mma16816(float* d, const uint32_t* a,
                                         const uint32_t* b) {
    asm("mma.sync.aligned.m16n8k16.row.col.f32.f16.f16.f32 "
        "{%0,%1,%2,%3}, {%4,%5,%6,%7}, {%8,%9}, {%0,%1,%2,%3};"
        : "+f"(d[0]), "+f"(d[1]), "+f"(d[2]), "+f"(d[3])
        : "r"(a[0]), "r"(a[1]), "r"(a[2]), "r"(a[3]),
          "r"(b[0]), "r"(b[1]));
}
__device__ __forceinline__ void pack_hl(float v0, float v1,
                                        uint32_t& hi, uint32_t& lo) {
    __half2 h = __floats2half2_rn(v0, v1);
    float2 f = __half22float2(h);
    __half2 l = __floats2half2_rn(v0 - f.x, v1 - f.y);
    hi = *(uint32_t*)&h;
    lo = *(uint32_t*)&l;
}

// ================= mma.sync GEMM ============================================
// C[M,N] = A @ B^T (B stored [N,K] K-major) + bias.
// TERMS: 2 -> (Ah+Al)@Bh, 1 -> Ah@Bh (plain fp16).
// SPLITOUT: 0 fp32 | 1 fp16 hi+lo | 2 fp16 hi | 3 QKV route (q hi+lo, k/v hi)
template<int ACT, int SPLITOUT, int TERMS>
__global__ __launch_bounds__(256, 2)
void gemm_mma(const __half* __restrict__ Ah,
              const __half* __restrict__ Al,
              const __half* __restrict__ Bh,
              const float* __restrict__ bias,
              float* __restrict__ C,
              __half* __restrict__ Ch,
              __half* __restrict__ Cl,
              __half* __restrict__ Kh_,
              __half* __restrict__ Vh_,
              int N, int K)
{
    constexpr int STAGE = (TERMS == 2) ? 49152 : 32768;
    constexpr uint32_t OFF_B = (TERMS == 2) ? 32768u : 16384u;
    extern __shared__ __align__(128) char smem[];
    const uint32_t sb = smem_u32(smem);
    const int tid  = threadIdx.x;
    const int wid  = tid >> 5;
    const int lane = tid & 31;
    const int wm   = wid & 3;
    const int wn   = wid >> 2;
    const int bc = blockIdx.x, br = blockIdx.y;

    const __half* Ah_t = Ah + (size_t)br * 128 * K;
    const __half* Al_t = (TERMS == 2) ? Al + (size_t)br * 128 * K : nullptr;
    const __half* Bh_t = Bh + (size_t)bc * 128 * K;
    const int NT = K >> 6;

    auto load_stage = [&](int kt, int s) {
        const uint32_t base = sb + s * STAGE;
        const int koff = kt * 64;
        #pragma unroll
        for (int t = 0; t < 4; t++) {
            int idx = t * 256 + tid;
            int row = idx >> 3, ch = idx & 7;
            uint32_t so = sw128((uint32_t)(row * 128 + ch * 16));
            size_t go = (size_t)row * K + koff + ch * 8;
            cp16(base + so, Ah_t + go);
            if (TERMS == 2) cp16(base + 16384 + so, Al_t + go);
            cp16(base + OFF_B + so, Bh_t + go);
        }
        CP_COMMIT();
    };

    float acc[2][8][4];
    #pragma unroll
    for (int mi = 0; mi < 2; mi++)
        #pragma unroll
        for (int nj = 0; nj < 8; nj++)
            #pragma unroll
            for (int e = 0; e < 4; e++) acc[mi][nj][e] = 0.f;

    const int g = lane >> 3, r = lane & 7;

    load_stage(0, 0);

    for (int kt = 0; kt < NT; kt++) {
        const int buf = kt & 1;
        if (kt + 1 < NT) { load_stage(kt + 1, buf ^ 1); CP_WAIT1(); }
        else             { CP_WAIT0(); }
        __syncthreads();

        const uint32_t sA  = sb + buf * STAGE;
        const uint32_t sAl = sA + 16384;
        const uint32_t sBh = sA + OFF_B;

        #pragma unroll
        for (int kc = 0; kc < 4; kc++) {
            uint32_t a_h[2][4], a_l[2][4];
            #pragma unroll
            for (int mi = 0; mi < 2; mi++) {
                int arow = wm * 32 + mi * 16 + r + ((g & 1) << 3);
                uint32_t off = sw128((uint32_t)(arow * 128 + kc * 32 +
                                                ((g >> 1) << 4)));
                ldsm4(a_h[mi], sA + off);
                if (TERMS == 2) ldsm4(a_l[mi], sAl + off);
            }
            uint32_t b_h[4][4];
            #pragma unroll
            for (int np = 0; np < 4; np++) {
                int brow = wn * 64 + np * 16 + r + ((g >> 1) << 3);
                uint32_t off = sw128((uint32_t)(brow * 128 + kc * 32 +
                                                ((g & 1) << 4)));
                ldsm4(b_h[np], sBh + off);
            }
            #pragma unroll
            for (int np = 0; np < 4; np++)
                #pragma unroll
                for (int t = 0; t < 2; t++)
                    #pragma unroll
                    for (int mi = 0; mi < 2; mi++)
                        mma16816(acc[mi][np * 2 + t], a_h[mi], &b_h[np][2 * t]);
            if (TERMS == 2) {
                #pragma unroll
                for (int np = 0; np < 4; np++)
                    #pragma unroll
                    for (int t = 0; t < 2; t++)
                        #pragma unroll
                        for (int mi = 0; mi < 2; mi++)
                            mma16816(acc[mi][np * 2 + t], a_l[mi], &b_h[np][2 * t]);
            }
        }
        __syncthreads();
    }

    const int rbase = br * 128 + wm * 32 + (lane >> 2);

    if (SPLITOUT == 3) {
        // QKV routing: bc 0-7 -> Q (hi+lo), 8-15 -> K (hi), 16-23 -> V (hi)
        const int sel   = bc >> 3;
        const int cloc0 = (bc & 7) * 128 + wn * 64 + (lane & 3) * 2;
        const int cgl0  = bc * 128 + wn * 64 + (lane & 3) * 2;
        #pragma unroll
        for (int mi = 0; mi < 2; mi++) {
            #pragma unroll
            for (int nj = 0; nj < 8; nj++) {
                float2 bv = *(const float2*)(bias + cgl0 + nj * 8);
                float v0 = acc[mi][nj][0] + bv.x;
                float v1 = acc[mi][nj][1] + bv.y;
                float v2 = acc[mi][nj][2] + bv.x;
                float v3 = acc[mi][nj][3] + bv.y;
                size_t i0 = (size_t)(rbase + mi * 16)     * DD + cloc0 + nj * 8;
                size_t i1 = (size_t)(rbase + mi * 16 + 8) * DD + cloc0 + nj * 8;
                if (sel == 0) {
                    uint32_t h0, l0, h1, l1;
                    pack_hl(v0, v1, h0, l0);
                    pack_hl(v2, v3, h1, l1);
                    *(uint32_t*)(Ch + i0) = h0;
                    *(uint32_t*)(Ch + i1) = h1;
                    *(uint32_t*)(Cl + i0) = l0;
                    *(uint32_t*)(Cl + i1) = l1;
                } else {
                    __half* dst = (sel == 1) ? Kh_ : Vh_;
                    *(__half2*)(dst + i0) = __floats2half2_rn(v0, v1);
                    *(__half2*)(dst + i1) = __floats2half2_rn(v2, v3);
                }
            }
        }
        return;
    }

    const int cbase = bc * 128 + wn * 64 + (lane & 3) * 2;
    #pragma unroll
    for (int mi = 0; mi < 2; mi++) {
        #pragma unroll
        for (int nj = 0; nj < 8; nj++) {
            int c = cbase + nj * 8;
            float2 bv = *(const float2*)(bias + c);
            float v0 = acc[mi][nj][0] + bv.x;
            float v1 = acc[mi][nj][1] + bv.y;
            float v2 = acc[mi][nj][2] + bv.x;
            float v3 = acc[mi][nj][3] + bv.y;
            if (ACT) {
                v0 = fmaxf(v0, 0.f); v1 = fmaxf(v1, 0.f);
                v2 = fmaxf(v2, 0.f); v3 = fmaxf(v3, 0.f);
            }
            size_t i0 = (size_t)(rbase + mi * 16)     * N + c;
            size_t i1 = (size_t)(rbase + mi * 16 + 8) * N + c;
            if (SPLITOUT == 1) {
                uint32_t h0, l0, h1, l1;
                pack_hl(v0, v1, h0, l0);
                pack_hl(v2, v3, h1, l1);
                *(uint32_t*)(Ch + i0) = h0;
                *(uint32_t*)(Ch + i1) = h1;
                *(uint32_t*)(Cl + i0) = l0;
                *(uint32_t*)(Cl + i1) = l1;
            } else if (SPLITOUT == 2) {
                *(__half2*)(Ch + i0) = __floats2half2_rn(v0, v1);
                *(__half2*)(Ch + i1) = __floats2half2_rn(v2, v3);
            } else {
                float2 o0; o0.x = v0; o0.y = v1;
                float2 o1; o1.x = v2; o1.y = v3;
                *(float2*)(C + i0) = o0;
                *(float2*)(C + i1) = o1;
            }
        }
    }
}

// ================= Flash attention (fp16, 2-term Q / P) =====================
#define A_QH   0
#define A_QL   16384
#define A_ST   32768            // 2 stages x (Kh 8K | Vh 8K)
#define A_MK   65536            // 2 x 256 B mask
#define A_SMEM (65536 + 512)

__global__ __launch_bounds__(256, 2)
void attn_mma(const __half* __restrict__ qh,
              const __half* __restrict__ ql,
              const __half* __restrict__ kh,
              const __half* __restrict__ vh,
              const float* __restrict__ mask,
              __half* __restrict__ ch,
              __half* __restrict__ cl)
{
    extern __shared__ __align__(128) char smem[];
    const uint32_t sb = smem_u32(smem);
    const int tid  = threadIdx.x;
    const int wid  = tid >> 5;
    const int lane = tid & 31;
    const int g    = lane >> 3, r8 = lane & 7;
    const int c2   = (lane & 3) * 2;

    const int qt = blockIdx.x;
    const int bh = blockIdx.y;
    const int b  = bh >> 4;
    const int h  = bh & 15;

    const size_t qrow0 = (size_t)b * SS + (size_t)qt * 128;
    const __half* qhg = qh + qrow0 * DD + h * DHH;
    const __half* qlg = ql + qrow0 * DD + h * DHH;
    const __half* khg = kh + (size_t)b * SS * DD + h * DHH;
    const __half* vhg = vh + (size_t)b * SS * DD + h * DHH;
    const float* mkg = mask + (size_t)b * SS;

    auto load_kv = [&](int t, int s) {
        const uint32_t base = sb + A_ST + s * 16384;
        const size_t koff = (size_t)(t * 64) * DD;
        #pragma unroll
        for (int it = 0; it < 4; it++) {
            int idx = it * 256 + tid;
            int mat = idx >> 9;
            int sub = idx & 511;
            int row = sub >> 3, chk = sub & 7;
            uint32_t so = sw128((uint32_t)(row * 128 + chk * 16));
            size_t go = koff + (size_t)row * DD + chk * 8;
            cp16(base + mat * 8192 + so, (mat ? vhg : khg) + go);
        }
        if (tid < 16)
            cp16(sb + A_MK + s * 256 + tid * 16, mkg + t * 64 + tid * 4);
        CP_COMMIT();
    };

    #pragma unroll
    for (int it = 0; it < 8; it++) {
        int idx = it * 256 + tid;
        int mat = idx >> 10;
        int sub = idx & 1023;
        int row = sub >> 3, chk = sub & 7;
        uint32_t so = sw128((uint32_t)(row * 128 + chk * 16));
        size_t go = (size_t)row * DD + chk * 8;
        cp16(sb + (mat ? A_QL : A_QH) + so, (mat ? qlg : qhg) + go);
    }
    load_kv(0, 0);

    float mA = -INFINITY, mB = -INFINITY, lA = 0.f, lB = 0.f;
    float O[8][4];
    #pragma unroll
    for (int j = 0; j < 8; j++)
        #pragma unroll
        for (int e = 0; e < 4; e++) O[j][e] = 0.f;

    #pragma unroll 1
    for (int t = 0; t < 16; t++) {
        const int buf = t & 1;
        if (t + 1 < 16) { load_kv(t + 1, buf ^ 1); CP_WAIT1(); }
        else            { CP_WAIT0(); }
        __syncthreads();

        const uint32_t sKh = sb + A_ST + buf * 16384;
        const uint32_t sVh = sKh + 8192;
        const float* mkv = (const float*)(smem + A_MK + buf * 256);

        float s_[8][4];
        #pragma unroll
        for (int j = 0; j < 8; j++)
            #pragma unroll
            for (int e = 0; e < 4; e++) s_[j][e] = 0.f;

        #pragma unroll
        for (int kc = 0; kc < 4; kc++) {
            uint32_t aqh[4], aql[4];
            {
                int arow = wid * 16 + r8 + ((g & 1) << 3);
                uint32_t off = sw128((uint32_t)(arow * 128 + kc * 32 +
                                                ((g >> 1) << 4)));
                ldsm4(aqh, sb + A_QH + off);
                ldsm4(aql, sb + A_QL + off);
            }
            uint32_t bkh[4][4];
            #pragma unroll
            for (int np = 0; np < 4; np++) {
                int brow = np * 16 + r8 + ((g >> 1) << 3);
                uint32_t off = sw128((uint32_t)(brow * 128 + kc * 32 +
                                                ((g & 1) << 4)));
                ldsm4(bkh[np], sKh + off);
            }
            #pragma unroll
            for (int np = 0; np < 4; np++)
                #pragma unroll
                for (int t2 = 0; t2 < 2; t2++)
                    mma16816(s_[np * 2 + t2], aqh, &bkh[np][2 * t2]);
            #pragma unroll
            for (int np = 0; np < 4; np++)
                #pragma unroll
                for (int t2 = 0; t2 < 2; t2++)
                    mma16816(s_[np * 2 + t2], aql, &bkh[np][2 * t2]);
        }

        float tmA = -INFINITY, tmB = -INFINITY;
        #pragma unroll
        for (int j = 0; j < 8; j++) {
            float mk0 = mkv[j * 8 + c2]     * (-1e9f);
            float mk1 = mkv[j * 8 + c2 + 1] * (-1e9f);
            s_[j][0] = s_[j][0] * 0.125f + mk0;
            s_[j][1] = s_[j][1] * 0.125f + mk1;
            s_[j][2] = s_[j][2] * 0.125f + mk0;
            s_[j][3] = s_[j][3] * 0.125f + mk1;
            tmA = fmaxf(tmA, fmaxf(s_[j][0], s_[j][1]));
            tmB = fmaxf(tmB, fmaxf(s_[j][2], s_[j][3]));
        }
        tmA = fmaxf(tmA, __shfl_xor_sync(0xffffffffu, tmA, 1));
        tmA = fmaxf(tmA, __shfl_xor_sync(0xffffffffu, tmA, 2));
        tmB = fmaxf(tmB, __shfl_xor_sync(0xffffffffu, tmB, 1));
        tmB = fmaxf(tmB, __shfl_xor_sync(0xffffffffu, tmB, 2));

        const float nmA = fmaxf(mA, tmA), nmB = fmaxf(mB, tmB);
        const float fA = __expf(mA - nmA), fB = __expf(mB - nmB);

        float sumA = 0.f, sumB = 0.f;
        #pragma unroll
        for (int j = 0; j < 8; j++) {
            s_[j][0] = __expf(s_[j][0] - nmA);
            s_[j][1] = __expf(s_[j][1] - nmA);
            s_[j][2] = __expf(s_[j][2] - nmB);
            s_[j][3] = __expf(s_[j][3] - nmB);
            sumA += s_[j][0] + s_[j][1];
            sumB += s_[j][2] + s_[j][3];
        }
        sumA += __shfl_xor_sync(0xffffffffu, sumA, 1);
        sumA += __shfl_xor_sync(0xffffffffu, sumA, 2);
        sumB += __shfl_xor_sync(0xffffffffu, sumB, 1);
        sumB += __shfl_xor_sync(0xffffffffu, sumB, 2);
        lA = lA * fA + sumA;  mA = nmA;
        lB = lB * fB + sumB;  mB = nmB;

        #pragma unroll
        for (int j = 0; j < 8; j++) {
            O[j][0] *= fA; O[j][1] *= fA;
            O[j][2] *= fB; O[j][3] *= fB;
        }

        #pragma unroll
        for (int c = 0; c < 4; c++) {
            uint32_t ap_h[4], ap_l[4];
            pack_hl(s_[2 * c][0],     s_[2 * c][1],     ap_h[0], ap_l[0]);
            pack_hl(s_[2 * c][2],     s_[2 * c][3],     ap_h[1], ap_l[1]);
            pack_hl(s_[2 * c + 1][0], s_[2 * c + 1][1], ap_h[2], ap_l[2]);
            pack_hl(s_[2 * c + 1][2], s_[2 * c + 1][3], ap_h[3], ap_l[3]);
            uint32_t bvh[4][4];
            #pragma unroll
            for (int np2 = 0; np2 < 4; np2++) {
                int vrow = c * 16 + r8 + ((g & 1) << 3);
                uint32_t off = sw128((uint32_t)(vrow * 128 + np2 * 32 +
                                                ((g >> 1) << 4)));
                ldsm4t(bvh[np2], sVh + off);
            }
            #pragma unroll
            for (int np2 = 0; np2 < 4; np2++)
                #pragma unroll
                for (int t2 = 0; t2 < 2; t2++)
                    mma16816(O[np2 * 2 + t2], ap_h, &bvh[np2][2 * t2]);
            #pragma unroll
            for (int np2 = 0; np2 < 4; np2++)
                #pragma unroll
                for (int t2 = 0; t2 < 2; t2++)
                    mma16816(O[np2 * 2 + t2], ap_l, &bvh[np2][2 * t2]);
        }
        __syncthreads();
    }

    const float liA = 1.f / lA, liB = 1.f / lB;
    const size_t rowA = qrow0 + wid * 16 + (lane >> 2);
    const size_t rowB = rowA + 8;
    const int    colb = h * DHH + c2;
    #pragma unroll
    for (int j = 0; j < 8; j++) {
        uint32_t hi, lo;
        pack_hl(O[j][0] * liA, O[j][1] * liA, hi, lo);
        *(uint32_t*)(ch + rowA * DD + colb + j * 8) = hi;
        *(uint32_t*)(cl + rowA * DD + colb + j * 8) = lo;
        pack_hl(O[j][2] * liB, O[j][3] * liB, hi, lo);
        *(uint32_t*)(ch + rowB * DD + colb + j * 8) = hi;
        *(uint32_t*)(cl + rowB * DD + colb + j * 8) = lo;
    }
}

// ================= fp32 -> fp16 hi/lo split =================================
__global__ __launch_bounds__(256) void split_kernel(
    const float4* __restrict__ in, __half2* __restrict__ oh,
    __half2* __restrict__ ol, int n4)
{
    int i = blockIdx.x * 256 + threadIdx.x;
    if (i >= n4) return;
    float4 v = in[i];
    uint32_t h0, l0, h1, l1;
    pack_hl(v.x, v.y, h0, l0);
    pack_hl(v.z, v.w, h1, l1);
    oh[2 * i]     = *(__half2*)&h0;
    oh[2 * i + 1] = *(__half2*)&h1;
    ol[2 * i]     = *(__half2*)&l0;
    ol[2 * i + 1] = *(__half2*)&l1;
}

// W[K,N] fp32 -> fp16 [N,K] (transpose)
__global__ __launch_bounds__(256) void split_tr_kernel(
    const float* __restrict__ W, __half* __restrict__ oh, int K, int N)
{
    __shared__ float t[32][33];
    const int bx = blockIdx.x, by = blockIdx.y;
    const int tx = threadIdx.x, ty = threadIdx.y;
    #pragma unroll
    for (int i = 0; i < 4; i++) {
        int rr = ty + i * 8;
        t[rr][tx] = W[(size_t)(by * 32 + rr) * N + bx * 32 + tx];
    }
    __syncthreads();
    #pragma unroll
    for (int i = 0; i < 4; i++) {
        int rr = ty + i * 8;
        size_t o = (size_t)(bx * 32 + rr) * K + by * 32 + tx;
        oh[o] = __float2half_rn(t[tx][rr]);
    }
}

__global__ void pack_bias_kernel(const float* __restrict__ b0,
                                 const float* __restrict__ b1,
                                 const float* __restrict__ b2,
                                 float* __restrict__ dst)
{
    const float* src = (blockIdx.x == 0) ? b0 : (blockIdx.x == 1) ? b1 : b2;
    dst[blockIdx.x * DD + threadIdx.x] = src[threadIdx.x];
}

// ================= residual + LayerNorm =====================================
// SPL==1: also emit fp16 hi (no lo needed downstream)
template<int SPL>
__global__ __launch_bounds__(256) void residual_ln_kernel(
    const float* __restrict__ X, const float* __restrict__ Y,
    const float* __restrict__ g, const float* __restrict__ beta,
    float* __restrict__ out, __half* __restrict__ oh)
{
    __shared__ float ws[8], ws2[8];
    const int row = blockIdx.x;
    const int tid = threadIdx.x;
    const int lane = tid & 31, warp = tid >> 5;
    const float* px = X + (size_t)row * DD;
    const float* py = Y + (size_t)row * DD;

    float v[4];
    float s = 0.f, s2 = 0.f;
    #pragma unroll
    for (int l = 0; l < 4; l++) {
        int c = tid + l * 256;
        float t = px[c] + py[c];
        v[l] = t; s += t; s2 += t * t;
    }
    #pragma unroll
    for (int off = 16; off; off >>= 1) {
        s  += __shfl_xor_sync(0xffffffffu, s,  off);
        s2 += __shfl_xor_sync(0xffffffffu, s2, off);
    }
    if (lane == 0) { ws[warp] = s; ws2[warp] = s2; }
    __syncthreads();
    if (warp == 0) {
        s  = (lane < 8) ? ws[lane]  : 0.f;
        s2 = (lane < 8) ? ws2[lane] : 0.f;
        #pragma unroll
        for (int off = 4; off; off >>= 1) {
            s  += __shfl_xor_sync(0xffffffffu, s,  off);
            s2 += __shfl_xor_sync(0xffffffffu, s2, off);
        }
        if (lane == 0) { ws[0] = s; ws2[0] = s2; }
    }
    __syncthreads();
    float mu  = ws[0] * (1.f / 1024.f);
    float var = fmaxf(ws2[0] * (1.f / 1024.f) - mu * mu, 0.f);
    float rstd = rsqrtf(var + 1e-6f);
    #pragma unroll
    for (int l = 0; l < 4; l++) {
        int c = tid + l * 256;
        float rv = g[c] * (v[l] - mu) * rstd + beta[c];
        out[(size_t)row * DD + c] = rv;
        if (SPL) oh[(size_t)row * DD + c] = __float2half_rn(rv);
    }
}

// ================= launch ===================================================
extern "C" void kernel_launch(void* const* d_in, const int* in_sizes, int n_in,
                              void* d_out, int out_size)
{
    const float* x    = (const float*)d_in[0];
    const float* mask = (const float*)d_in[1];
    const float* Wq   = (const float*)d_in[2];
    const float* bq   = (const float*)d_in[3];
    const float* Wk   = (const float*)d_in[4];
    const float* bk   = (const float*)d_in[5];
    const float* Wv   = (const float*)d_in[6];
    const float* bv   = (const float*)d_in[7];
    const float* Wo   = (const float*)d_in[8];
    const float* bo   = (const float*)d_in[9];
    const float* g1   = (const float*)d_in[10];
    const float* be1  = (const float*)d_in[11];
    const float* W1   = (const float*)d_in[12];
    const float* bf1  = (const float*)d_in[13];
    const float* W2   = (const float*)d_in[14];
    const float* bf2  = (const float*)d_in[15];
    const float* g2   = (const float*)d_in[16];
    const float* be2  = (const float*)d_in[17];
    float* out = (float*)d_out;

    float *t1, *x1, *bqkv;
    __half *ah, *al, *qh, *ql, *kh, *vh, *hh;
    __half *wqkv, *woh, *w1h, *w2h;
    cudaGetSymbolAddress((void**)&t1,   g_t1);
    cudaGetSymbolAddress((void**)&x1,   g_x1);
    cudaGetSymbolAddress((void**)&ah,   g_ah);
    cudaGetSymbolAddress((void**)&al,   g_al);
    cudaGetSymbolAddress((void**)&qh,   g_qh);
    cudaGetSymbolAddress((void**)&ql,   g_ql);
    cudaGetSymbolAddress((void**)&kh,   g_kh);
    cudaGetSymbolAddress((void**)&vh,   g_vh);
    cudaGetSymbolAddress((void**)&hh,   g_hh);
    cudaGetSymbolAddress((void**)&wqkv, g_wqkv);
    cudaGetSymbolAddress((void**)&bqkv, g_bqkv);
    cudaGetSymbolAddress((void**)&woh,  g_woh);
    cudaGetSymbolAddress((void**)&w1h,  g_w1h);
    cudaGetSymbolAddress((void**)&w2h,  g_w2h);

    cudaFuncSetAttribute(attn_mma,
                         cudaFuncAttributeMaxDynamicSharedMemorySize, A_SMEM);
    cudaFuncSetAttribute(gemm_mma<0, 3, 2>,
                         cudaFuncAttributeMaxDynamicSharedMemorySize, 2 * 49152);
    cudaFuncSetAttribute(gemm_mma<0, 0, 2>,
                         cudaFuncAttributeMaxDynamicSharedMemorySize, 2 * 49152);
    cudaFuncSetAttribute(gemm_mma<1, 2, 1>,
                         cudaFuncAttributeMaxDynamicSharedMemorySize, 2 * 32768);
    cudaFuncSetAttribute(gemm_mma<0, 0, 1>,
                         cudaFuncAttributeMaxDynamicSharedMemorySize, 2 * 32768);

    static cudaStream_t s2 = nullptr;
    static cudaEvent_t evF, evQKVp, evO, ev1p, ev2p;
    if (!s2) {
        cudaStreamCreateWithFlags(&s2, cudaStreamNonBlocking);
        cudaEventCreateWithFlags(&evF,    cudaEventDisableTiming);
        cudaEventCreateWithFlags(&evQKVp, cudaEventDisableTiming);
        cudaEventCreateWithFlags(&evO,    cudaEventDisableTiming);
        cudaEventCreateWithFlags(&ev1p,   cudaEventDisableTiming);
        cudaEventCreateWithFlags(&ev2p,   cudaEventDisableTiming);
    }

    const dim3 trDD(DD / 32, DD / 32);
    const dim3 trDF(FF / 32, DD / 32);
    const dim3 trFD(DD / 32, FF / 32);
    const dim3 tb(32, 8);
    const dim3 gQKV(3 * DD / 128, MR / 128);  // (24, 64)
    const dim3 gD(DD / 128, MR / 128);        // (8, 64)
    const dim3 gF(FF / 128, MR / 128);        // (32, 64)

    // ---- fork: weight prep on side stream ----
    cudaEventRecord(evF, 0);
    cudaStreamWaitEvent(s2, evF, 0);
    split_tr_kernel<<<trDD, tb, 0, s2>>>(Wq, wqkv,               DD, DD);
    split_tr_kernel<<<trDD, tb, 0, s2>>>(Wk, wqkv + DD * DD,     DD, DD);
    split_tr_kernel<<<trDD, tb, 0, s2>>>(Wv, wqkv + 2 * DD * DD, DD, DD);
    pack_bias_kernel<<<3, DD, 0, s2>>>(bq, bk, bv, bqkv);
    cudaEventRecord(evQKVp, s2);
    split_tr_kernel<<<trDD, tb, 0, s2>>>(Wo, woh, DD, DD);
    cudaEventRecord(evO, s2);
    split_tr_kernel<<<trDF, tb, 0, s2>>>(W1, w1h, DD, FF);
    cudaEventRecord(ev1p, s2);
    split_tr_kernel<<<trFD, tb, 0, s2>>>(W2, w2h, FF, DD);
    cudaEventRecord(ev2p, s2);

    // ---- main stream ----
    split_kernel<<<(MR * DD / 4 + 255) / 256, 256>>>(
        (const float4*)x, (__half2*)ah, (__half2*)al, MR * DD / 4);

    // fused QKV projection
    cudaStreamWaitEvent(0, evQKVp, 0);
    gemm_mma<0, 3, 2><<<gQKV, 256, 2 * 49152>>>(
        ah, al, wqkv, bqkv, nullptr, qh, ql, kh, vh, 3 * DD, DD);

    // attention -> split ctx into ah/al
    attn_mma<<<dim3(8, 128), 256, A_SMEM>>>(qh, ql, kh, vh, mask, ah, al);

    // output projection + residual LN (emits fp16-hi x1 into ah)
    cudaStreamWaitEvent(0, evO, 0);
    gemm_mma<0, 0, 2><<<gD, 256, 2 * 49152>>>(
        ah, al, woh, bo, t1, nullptr, nullptr, nullptr, nullptr, DD, DD);
    residual_ln_kernel<1><<<MR, 256>>>(x, t1, g1, be1, x1, ah);

    // FFN1 (1-term): relu(x1 @ W1 + bf1) -> fp16 hidden (hi only)
    cudaStreamWaitEvent(0, ev1p, 0);
    gemm_mma<1, 2, 1><<<gF, 256, 2 * 32768>>>(
        ah, nullptr, w1h, bf1, nullptr, hh, nullptr, nullptr, nullptr, FF, DD);

    // FFN2 (1-term) + residual LN
    cudaStreamWaitEvent(0, ev2p, 0);
    gemm_mma<0, 0, 1><<<gD, 256, 2 * 32768>>>(
        hh, nullptr, w2h, bf2, t1, nullptr, nullptr, nullptr, nullptr, DD, FF);
    residual_ln_kernel<0><<<MR, 256>>>(x1, t1, g2, be2, out, nullptr);
}

// round 9
// speedup vs baseline: 2.6046x; 1.2987x over previous
#include <cuda_runtime.h>
#include <cuda_fp16.h>
#include <math.h>
#include <stddef.h>
#include <stdint.h>

#define BB   8
#define SS   1024
#define DD   1024
#define HH   16
#define DHH  64
#define FF   4096
#define MR   (BB*SS)   // 8192 rows

// ---------------- scratch (device globals) ----------------------------------
__device__ float g_t1 [MR*DD];
__device__ float g_x1 [MR*DD];

__device__ __half g_ah[MR*DD];            // activation fp16 (x / ctx / x1)
__device__ __half g_qh[MR*DD];
__device__ __half g_kh[MR*DD];
__device__ __half g_vh[MR*DD];
__device__ __half g_hh[(size_t)MR*FF];    // FFN hidden
// weights, [N,K] K-major
__device__ __half g_wqkv[3*DD*DD];        // packed Wq|Wk|Wv
__device__ float  g_bqkv[3*DD];           // packed bq|bk|bv
__device__ __half g_woh[DD*DD];
__device__ __half g_w1h[(size_t)DD*FF];
__device__ __half g_w2h[(size_t)FF*DD];

// ================= PTX helpers ==============================================
__device__ __forceinline__ uint32_t smem_u32(const void* p) {
    uint32_t a;
    asm("{ .reg .u64 t; cvta.to.shared.u64 t, %1; cvt.u32.u64 %0, t; }"
        : "=r"(a) : "l"(p));
    return a;
}
__device__ __forceinline__ uint32_t sw128(uint32_t o) {
    return o ^ ((o >> 3) & 0x70);
}
__device__ __forceinline__ void cp16(uint32_t s, const void* g) {
    asm volatile("cp.async.cg.shared.global [%0], [%1], 16;" :: "r"(s), "l"(g));
}
#define CP_COMMIT()  asm volatile("cp.async.commit_group;" ::: "memory")
#define CP_WAIT0()   asm volatile("cp.async.wait_group 0;" ::: "memory")
#define CP_WAIT1()   asm volatile("cp.async.wait_group 1;" ::: "memory")

__device__ __forceinline__ void ldsm4(uint32_t* r, uint32_t addr) {
    asm volatile("ldmatrix.sync.aligned.m8n8.x4.shared.b16 {%0,%1,%2,%3}, [%4];"
                 : "=r"(r[0]), "=r"(r[1]), "=r"(r[2]), "=r"(r[3]) : "r"(addr));
}
__device__ __forceinline__ void ldsm4t(uint32_t* r, uint32_t addr) {
    asm volatile("ldmatrix.sync.aligned.m8n8.x4.trans.shared.b16 {%0,%1,%2,%3}, [%4];"
                 : "=r"(r[0]), "=r"(r[1]), "=r"(r[2]), "=r"(r[3]) : "r"(addr));
}
__device__ __forceinline__ void mma16816(float* d, const uint32_t* a,
                                         const uint32_t* b) {
    asm("mma.sync.aligned.m16n8k16.row.col.f32.f16.f16.f32 "
        "{%0,%1,%2,%3}, {%4,%5,%6,%7}, {%8,%9}, {%0,%1,%2,%3};"
        : "+f"(d[0]), "+f"(d[1]), "+f"(d[2]), "+f"(d[3])
        : "r"(a[0]), "r"(a[1]), "r"(a[2]), "r"(a[3]),
          "r"(b[0]), "r"(b[1]));
}

// ================= mma.sync GEMM (plain fp16, fp32 accum) ===================
// C[M,N] = A @ B^T (B stored [N,K] K-major) + bias.
// SPLITOUT: 0 fp32 C | 2 fp16 C | 3 QKV route (q/k/v fp16)
#define G_STAGE  32768            // A 16K | B 16K
#define G_SMEM   (2*G_STAGE)      // 64 KB

template<int ACT, int SPLITOUT>
__global__ __launch_bounds__(256, 2)
void gemm_mma(const __half* __restrict__ Ah,
              const __half* __restrict__ Bh,
              const float* __restrict__ bias,
              float* __restrict__ C,
              __half* __restrict__ Ch,
              __half* __restrict__ Kh_,
              __half* __restrict__ Vh_,
              int N, int K)
{
    extern __shared__ __align__(128) char smem[];
    const uint32_t sb = smem_u32(smem);
    const int tid  = threadIdx.x;
    const int wid  = tid >> 5;
    const int lane = tid & 31;
    const int wm   = wid & 3;
    const int wn   = wid >> 2;
    const int bc = blockIdx.x, br = blockIdx.y;

    const __half* Ah_t = Ah + (size_t)br * 128 * K;
    const __half* Bh_t = Bh + (size_t)bc * 128 * K;
    const int NT = K >> 6;

    auto load_stage = [&](int kt, int s) {
        const uint32_t base = sb + s * G_STAGE;
        const int koff = kt * 64;
        #pragma unroll
        for (int t = 0; t < 4; t++) {
            int idx = t * 256 + tid;
            int row = idx >> 3, ch = idx & 7;
            uint32_t so = sw128((uint32_t)(row * 128 + ch * 16));
            size_t go = (size_t)row * K + koff + ch * 8;
            cp16(base + so,         Ah_t + go);
            cp16(base + 16384 + so, Bh_t + go);
        }
        CP_COMMIT();
    };

    float acc[2][8][4];
    #pragma unroll
    for (int mi = 0; mi < 2; mi++)
        #pragma unroll
        for (int nj = 0; nj < 8; nj++)
            #pragma unroll
            for (int e = 0; e < 4; e++) acc[mi][nj][e] = 0.f;

    const int g = lane >> 3, r = lane & 7;

    load_stage(0, 0);

    for (int kt = 0; kt < NT; kt++) {
        const int buf = kt & 1;
        if (kt + 1 < NT) { load_stage(kt + 1, buf ^ 1); CP_WAIT1(); }
        else             { CP_WAIT0(); }
        __syncthreads();

        const uint32_t sA  = sb + buf * G_STAGE;
        const uint32_t sBh = sA + 16384;

        #pragma unroll
        for (int kc = 0; kc < 4; kc++) {
            uint32_t a_h[2][4];
            #pragma unroll
            for (int mi = 0; mi < 2; mi++) {
                int arow = wm * 32 + mi * 16 + r + ((g & 1) << 3);
                uint32_t off = sw128((uint32_t)(arow * 128 + kc * 32 +
                                                ((g >> 1) << 4)));
                ldsm4(a_h[mi], sA + off);
            }
            uint32_t b_h[4][4];
            #pragma unroll
            for (int np = 0; np < 4; np++) {
                int brow = wn * 64 + np * 16 + r + ((g >> 1) << 3);
                uint32_t off = sw128((uint32_t)(brow * 128 + kc * 32 +
                                                ((g & 1) << 4)));
                ldsm4(b_h[np], sBh + off);
            }
            #pragma unroll
            for (int np = 0; np < 4; np++)
                #pragma unroll
                for (int t = 0; t < 2; t++)
                    #pragma unroll
                    for (int mi = 0; mi < 2; mi++)
                        mma16816(acc[mi][np * 2 + t], a_h[mi], &b_h[np][2 * t]);
        }
        __syncthreads();
    }

    const int rbase = br * 128 + wm * 32 + (lane >> 2);

    if (SPLITOUT == 3) {
        // QKV routing: bc 0-7 -> Q, 8-15 -> K, 16-23 -> V (all fp16)
        const int sel   = bc >> 3;
        const int cloc0 = (bc & 7) * 128 + wn * 64 + (lane & 3) * 2;
        const int cgl0  = bc * 128 + wn * 64 + (lane & 3) * 2;
        __half* dst = (sel == 0) ? Ch : (sel == 1) ? Kh_ : Vh_;
        #pragma unroll
        for (int mi = 0; mi < 2; mi++) {
            #pragma unroll
            for (int nj = 0; nj < 8; nj++) {
                float2 bv = *(const float2*)(bias + cgl0 + nj * 8);
                float v0 = acc[mi][nj][0] + bv.x;
                float v1 = acc[mi][nj][1] + bv.y;
                float v2 = acc[mi][nj][2] + bv.x;
                float v3 = acc[mi][nj][3] + bv.y;
                size_t i0 = (size_t)(rbase + mi * 16)     * DD + cloc0 + nj * 8;
                size_t i1 = (size_t)(rbase + mi * 16 + 8) * DD + cloc0 + nj * 8;
                *(__half2*)(dst + i0) = __floats2half2_rn(v0, v1);
                *(__half2*)(dst + i1) = __floats2half2_rn(v2, v3);
            }
        }
        return;
    }

    const int cbase = bc * 128 + wn * 64 + (lane & 3) * 2;
    #pragma unroll
    for (int mi = 0; mi < 2; mi++) {
        #pragma unroll
        for (int nj = 0; nj < 8; nj++) {
            int c = cbase + nj * 8;
            float2 bv = *(const float2*)(bias + c);
            float v0 = acc[mi][nj][0] + bv.x;
            float v1 = acc[mi][nj][1] + bv.y;
            float v2 = acc[mi][nj][2] + bv.x;
            float v3 = acc[mi][nj][3] + bv.y;
            if (ACT) {
                v0 = fmaxf(v0, 0.f); v1 = fmaxf(v1, 0.f);
                v2 = fmaxf(v2, 0.f); v3 = fmaxf(v3, 0.f);
            }
            size_t i0 = (size_t)(rbase + mi * 16)     * N + c;
            size_t i1 = (size_t)(rbase + mi * 16 + 8) * N + c;
            if (SPLITOUT == 2) {
                *(__half2*)(Ch + i0) = __floats2half2_rn(v0, v1);
                *(__half2*)(Ch + i1) = __floats2half2_rn(v2, v3);
            } else {
                float2 o0; o0.x = v0; o0.y = v1;
                float2 o1; o1.x = v2; o1.y = v3;
                *(float2*)(C + i0) = o0;
                *(float2*)(C + i1) = o1;
            }
        }
    }
}

// ================= Flash attention (pure fp16, fp32 softmax) ================
#define A_QH   0
#define A_ST   16384            // 2 stages x (Kh 8K | Vh 8K)
#define A_MK   49152            // 2 x 256 B mask
#define A_SMEM (49152 + 512)

__global__ __launch_bounds__(256, 2)
void attn_mma(const __half* __restrict__ qh,
              const __half* __restrict__ kh,
              const __half* __restrict__ vh,
              const float* __restrict__ mask,
              __half* __restrict__ ch)
{
    extern __shared__ __align__(128) char smem[];
    const uint32_t sb = smem_u32(smem);
    const int tid  = threadIdx.x;
    const int wid  = tid >> 5;
    const int lane = tid & 31;
    const int g    = lane >> 3, r8 = lane & 7;
    const int c2   = (lane & 3) * 2;

    const int qt = blockIdx.x;
    const int bh = blockIdx.y;
    const int b  = bh >> 4;
    const int h  = bh & 15;

    const size_t qrow0 = (size_t)b * SS + (size_t)qt * 128;
    const __half* qhg = qh + qrow0 * DD + h * DHH;
    const __half* khg = kh + (size_t)b * SS * DD + h * DHH;
    const __half* vhg = vh + (size_t)b * SS * DD + h * DHH;
    const float* mkg = mask + (size_t)b * SS;

    auto load_kv = [&](int t, int s) {
        const uint32_t base = sb + A_ST + s * 16384;
        const size_t koff = (size_t)(t * 64) * DD;
        #pragma unroll
        for (int it = 0; it < 4; it++) {
            int idx = it * 256 + tid;
            int mat = idx >> 9;
            int sub = idx & 511;
            int row = sub >> 3, chk = sub & 7;
            uint32_t so = sw128((uint32_t)(row * 128 + chk * 16));
            size_t go = koff + (size_t)row * DD + chk * 8;
            cp16(base + mat * 8192 + so, (mat ? vhg : khg) + go);
        }
        if (tid < 16)
            cp16(sb + A_MK + s * 256 + tid * 16, mkg + t * 64 + tid * 4);
        CP_COMMIT();
    };

    // Q tile load (128 rows x 128 B)
    #pragma unroll
    for (int it = 0; it < 4; it++) {
        int idx = it * 256 + tid;
        int row = idx >> 3, chk = idx & 7;
        uint32_t so = sw128((uint32_t)(row * 128 + chk * 16));
        cp16(sb + A_QH + so, qhg + (size_t)row * DD + chk * 8);
    }
    load_kv(0, 0);

    float mA = -INFINITY, mB = -INFINITY, lA = 0.f, lB = 0.f;
    float O[8][4];
    #pragma unroll
    for (int j = 0; j < 8; j++)
        #pragma unroll
        for (int e = 0; e < 4; e++) O[j][e] = 0.f;

    #pragma unroll 1
    for (int t = 0; t < 16; t++) {
        const int buf = t & 1;
        if (t + 1 < 16) { load_kv(t + 1, buf ^ 1); CP_WAIT1(); }
        else            { CP_WAIT0(); }
        __syncthreads();

        const uint32_t sKh = sb + A_ST + buf * 16384;
        const uint32_t sVh = sKh + 8192;
        const float* mkv = (const float*)(smem + A_MK + buf * 256);

        // ---- S = Q @ K^T ----
        float s_[8][4];
        #pragma unroll
        for (int j = 0; j < 8; j++)
            #pragma unroll
            for (int e = 0; e < 4; e++) s_[j][e] = 0.f;

        #pragma unroll
        for (int kc = 0; kc < 4; kc++) {
            uint32_t aqh[4];
            {
                int arow = wid * 16 + r8 + ((g & 1) << 3);
                uint32_t off = sw128((uint32_t)(arow * 128 + kc * 32 +
                                                ((g >> 1) << 4)));
                ldsm4(aqh, sb + A_QH + off);
            }
            uint32_t bkh[4][4];
            #pragma unroll
            for (int np = 0; np < 4; np++) {
                int brow = np * 16 + r8 + ((g >> 1) << 3);
                uint32_t off = sw128((uint32_t)(brow * 128 + kc * 32 +
                                                ((g & 1) << 4)));
                ldsm4(bkh[np], sKh + off);
            }
            #pragma unroll
            for (int np = 0; np < 4; np++)
                #pragma unroll
                for (int t2 = 0; t2 < 2; t2++)
                    mma16816(s_[np * 2 + t2], aqh, &bkh[np][2 * t2]);
        }

        // ---- scale + mask, row max ----
        float tmA = -INFINITY, tmB = -INFINITY;
        #pragma unroll
        for (int j = 0; j < 8; j++) {
            float mk0 = mkv[j * 8 + c2]     * (-1e9f);
            float mk1 = mkv[j * 8 + c2 + 1] * (-1e9f);
            s_[j][0] = s_[j][0] * 0.125f + mk0;
            s_[j][1] = s_[j][1] * 0.125f + mk1;
            s_[j][2] = s_[j][2] * 0.125f + mk0;
            s_[j][3] = s_[j][3] * 0.125f + mk1;
            tmA = fmaxf(tmA, fmaxf(s_[j][0], s_[j][1]));
            tmB = fmaxf(tmB, fmaxf(s_[j][2], s_[j][3]));
        }
        tmA = fmaxf(tmA, __shfl_xor_sync(0xffffffffu, tmA, 1));
        tmA = fmaxf(tmA, __shfl_xor_sync(0xffffffffu, tmA, 2));
        tmB = fmaxf(tmB, __shfl_xor_sync(0xffffffffu, tmB, 1));
        tmB = fmaxf(tmB, __shfl_xor_sync(0xffffffffu, tmB, 2));

        const float nmA = fmaxf(mA, tmA), nmB = fmaxf(mB, tmB);
        const float fA = __expf(mA - nmA), fB = __expf(mB - nmB);

        float sumA = 0.f, sumB = 0.f;
        #pragma unroll
        for (int j = 0; j < 8; j++) {
            s_[j][0] = __expf(s_[j][0] - nmA);
            s_[j][1] = __expf(s_[j][1] - nmA);
            s_[j][2] = __expf(s_[j][2] - nmB);
            s_[j][3] = __expf(s_[j][3] - nmB);
            sumA += s_[j][0] + s_[j][1];
            sumB += s_[j][2] + s_[j][3];
        }
        sumA += __shfl_xor_sync(0xffffffffu, sumA, 1);
        sumA += __shfl_xor_sync(0xffffffffu, sumA, 2);
        sumB += __shfl_xor_sync(0xffffffffu, sumB, 1);
        sumB += __shfl_xor_sync(0xffffffffu, sumB, 2);
        lA = lA * fA + sumA;  mA = nmA;
        lB = lB * fB + sumB;  mB = nmB;

        #pragma unroll
        for (int j = 0; j < 8; j++) {
            O[j][0] *= fA; O[j][1] *= fA;
            O[j][2] *= fB; O[j][3] *= fB;
        }

        // ---- O += P @ V (P in fp16) ----
        #pragma unroll
        for (int c = 0; c < 4; c++) {
            uint32_t ap_h[4];
            __half2 p0 = __floats2half2_rn(s_[2 * c][0],     s_[2 * c][1]);
            __half2 p1 = __floats2half2_rn(s_[2 * c][2],     s_[2 * c][3]);
            __half2 p2 = __floats2half2_rn(s_[2 * c + 1][0], s_[2 * c + 1][1]);
            __half2 p3 = __floats2half2_rn(s_[2 * c + 1][2], s_[2 * c + 1][3]);
            ap_h[0] = *(uint32_t*)&p0; ap_h[1] = *(uint32_t*)&p1;
            ap_h[2] = *(uint32_t*)&p2; ap_h[3] = *(uint32_t*)&p3;
            uint32_t bvh[4][4];
            #pragma unroll
            for (int np2 = 0; np2 < 4; np2++) {
                int vrow = c * 16 + r8 + ((g & 1) << 3);
                uint32_t off = sw128((uint32_t)(vrow * 128 + np2 * 32 +
                                                ((g >> 1) << 4)));
                ldsm4t(bvh[np2], sVh + off);
            }
            #pragma unroll
            for (int np2 = 0; np2 < 4; np2++)
                #pragma unroll
                for (int t2 = 0; t2 < 2; t2++)
                    mma16816(O[np2 * 2 + t2], ap_h, &bvh[np2][2 * t2]);
        }
        __syncthreads();
    }

    // ---- normalize, write fp16 ctx ----
    const float liA = 1.f / lA, liB = 1.f / lB;
    const size_t rowA = qrow0 + wid * 16 + (lane >> 2);
    const size_t rowB = rowA + 8;
    const int    colb = h * DHH + c2;
    #pragma unroll
    for (int j = 0; j < 8; j++) {
        *(__half2*)(ch + rowA * DD + colb + j * 8) =
            __floats2half2_rn(O[j][0] * liA, O[j][1] * liA);
        *(__half2*)(ch + rowB * DD + colb + j * 8) =
            __floats2half2_rn(O[j][2] * liB, O[j][3] * liB);
    }
}

// ================= fp32 -> fp16 convert =====================================
__global__ __launch_bounds__(256) void convert_kernel(
    const float4* __restrict__ in, __half2* __restrict__ oh, int n4)
{
    int i = blockIdx.x * 256 + threadIdx.x;
    if (i >= n4) return;
    float4 v = in[i];
    oh[2 * i]     = __floats2half2_rn(v.x, v.y);
    oh[2 * i + 1] = __floats2half2_rn(v.z, v.w);
}

// W[K,N] fp32 -> fp16 [N,K] (transpose)
__global__ __launch_bounds__(256) void split_tr_kernel(
    const float* __restrict__ W, __half* __restrict__ oh, int K, int N)
{
    __shared__ float t[32][33];
    const int bx = blockIdx.x, by = blockIdx.y;
    const int tx = threadIdx.x, ty = threadIdx.y;
    #pragma unroll
    for (int i = 0; i < 4; i++) {
        int rr = ty + i * 8;
        t[rr][tx] = W[(size_t)(by * 32 + rr) * N + bx * 32 + tx];
    }
    __syncthreads();
    #pragma unroll
    for (int i = 0; i < 4; i++) {
        int rr = ty + i * 8;
        size_t o = (size_t)(bx * 32 + rr) * K + by * 32 + tx;
        oh[o] = __float2half_rn(t[tx][rr]);
    }
}

__global__ void pack_bias_kernel(const float* __restrict__ b0,
                                 const float* __restrict__ b1,
                                 const float* __restrict__ b2,
                                 float* __restrict__ dst)
{
    const float* src = (blockIdx.x == 0) ? b0 : (blockIdx.x == 1) ? b1 : b2;
    dst[blockIdx.x * DD + threadIdx.x] = src[threadIdx.x];
}

// ================= residual + LayerNorm =====================================
template<int SPL>
__global__ __launch_bounds__(256) void residual_ln_kernel(
    const float* __restrict__ X, const float* __restrict__ Y,
    const float* __restrict__ g, const float* __restrict__ beta,
    float* __restrict__ out, __half* __restrict__ oh)
{
    __shared__ float ws[8], ws2[8];
    const int row = blockIdx.x;
    const int tid = threadIdx.x;
    const int lane = tid & 31, warp = tid >> 5;
    const float* px = X + (size_t)row * DD;
    const float* py = Y + (size_t)row * DD;

    float v[4];
    float s = 0.f, s2 = 0.f;
    #pragma unroll
    for (int l = 0; l < 4; l++) {
        int c = tid + l * 256;
        float t = px[c] + py[c];
        v[l] = t; s += t; s2 += t * t;
    }
    #pragma unroll
    for (int off = 16; off; off >>= 1) {
        s  += __shfl_xor_sync(0xffffffffu, s,  off);
        s2 += __shfl_xor_sync(0xffffffffu, s2, off);
    }
    if (lane == 0) { ws[warp] = s; ws2[warp] = s2; }
    __syncthreads();
    if (warp == 0) {
        s  = (lane < 8) ? ws[lane]  : 0.f;
        s2 = (lane < 8) ? ws2[lane] : 0.f;
        #pragma unroll
        for (int off = 4; off; off >>= 1) {
            s  += __shfl_xor_sync(0xffffffffu, s,  off);
            s2 += __shfl_xor_sync(0xffffffffu, s2, off);
        }
        if (lane == 0) { ws[0] = s; ws2[0] = s2; }
    }
    __syncthreads();
    float mu  = ws[0] * (1.f / 1024.f);
    float var = fmaxf(ws2[0] * (1.f / 1024.f) - mu * mu, 0.f);
    float rstd = rsqrtf(var + 1e-6f);
    #pragma unroll
    for (int l = 0; l < 4; l++) {
        int c = tid + l * 256;
        float rv = g[c] * (v[l] - mu) * rstd + beta[c];
        out[(size_t)row * DD + c] = rv;
        if (SPL) oh[(size_t)row * DD + c] = __float2half_rn(rv);
    }
}

// ================= launch ===================================================
extern "C" void kernel_launch(void* const* d_in, const int* in_sizes, int n_in,
                              void* d_out, int out_size)
{
    const float* x    = (const float*)d_in[0];
    const float* mask = (const float*)d_in[1];
    const float* Wq   = (const float*)d_in[2];
    const float* bq   = (const float*)d_in[3];
    const float* Wk   = (const float*)d_in[4];
    const float* bk   = (const float*)d_in[5];
    const float* Wv   = (const float*)d_in[6];
    const float* bv   = (const float*)d_in[7];
    const float* Wo   = (const float*)d_in[8];
    const float* bo   = (const float*)d_in[9];
    const float* g1   = (const float*)d_in[10];
    const float* be1  = (const float*)d_in[11];
    const float* W1   = (const float*)d_in[12];
    const float* bf1  = (const float*)d_in[13];
    const float* W2   = (const float*)d_in[14];
    const float* bf2  = (const float*)d_in[15];
    const float* g2   = (const float*)d_in[16];
    const float* be2  = (const float*)d_in[17];
    float* out = (float*)d_out;

    float *t1, *x1, *bqkv;
    __half *ah, *qh, *kh, *vh, *hh;
    __half *wqkv, *woh, *w1h, *w2h;
    cudaGetSymbolAddress((void**)&t1,   g_t1);
    cudaGetSymbolAddress((void**)&x1,   g_x1);
    cudaGetSymbolAddress((void**)&ah,   g_ah);
    cudaGetSymbolAddress((void**)&qh,   g_qh);
    cudaGetSymbolAddress((void**)&kh,   g_kh);
    cudaGetSymbolAddress((void**)&vh,   g_vh);
    cudaGetSymbolAddress((void**)&hh,   g_hh);
    cudaGetSymbolAddress((void**)&wqkv, g_wqkv);
    cudaGetSymbolAddress((void**)&bqkv, g_bqkv);
    cudaGetSymbolAddress((void**)&woh,  g_woh);
    cudaGetSymbolAddress((void**)&w1h,  g_w1h);
    cudaGetSymbolAddress((void**)&w2h,  g_w2h);

    cudaFuncSetAttribute(attn_mma,
                         cudaFuncAttributeMaxDynamicSharedMemorySize, A_SMEM);
    cudaFuncSetAttribute(gemm_mma<0, 3>,
                         cudaFuncAttributeMaxDynamicSharedMemorySize, G_SMEM);
    cudaFuncSetAttribute(gemm_mma<0, 0>,
                         cudaFuncAttributeMaxDynamicSharedMemorySize, G_SMEM);
    cudaFuncSetAttribute(gemm_mma<1, 2>,
                         cudaFuncAttributeMaxDynamicSharedMemorySize, G_SMEM);

    static cudaStream_t s2 = nullptr;
    static cudaEvent_t evF, evQKVp, evO, ev1p, ev2p;
    if (!s2) {
        cudaStreamCreateWithFlags(&s2, cudaStreamNonBlocking);
        cudaEventCreateWithFlags(&evF,    cudaEventDisableTiming);
        cudaEventCreateWithFlags(&evQKVp, cudaEventDisableTiming);
        cudaEventCreateWithFlags(&evO,    cudaEventDisableTiming);
        cudaEventCreateWithFlags(&ev1p,   cudaEventDisableTiming);
        cudaEventCreateWithFlags(&ev2p,   cudaEventDisableTiming);
    }

    const dim3 trDD(DD / 32, DD / 32);
    const dim3 trDF(FF / 32, DD / 32);
    const dim3 trFD(DD / 32, FF / 32);
    const dim3 tb(32, 8);
    const dim3 gQKV(3 * DD / 128, MR / 128);  // (24, 64)
    const dim3 gD(DD / 128, MR / 128);        // (8, 64)
    const dim3 gF(FF / 128, MR / 128);        // (32, 64)

    // ---- fork: weight prep on side stream ----
    cudaEventRecord(evF, 0);
    cudaStreamWaitEvent(s2, evF, 0);
    split_tr_kernel<<<trDD, tb, 0, s2>>>(Wq, wqkv,               DD, DD);
    split_tr_kernel<<<trDD, tb, 0, s2>>>(Wk, wqkv + DD * DD,     DD, DD);
    split_tr_kernel<<<trDD, tb, 0, s2>>>(Wv, wqkv + 2 * DD * DD, DD, DD);
    pack_bias_kernel<<<3, DD, 0, s2>>>(bq, bk, bv, bqkv);
    cudaEventRecord(evQKVp, s2);
    split_tr_kernel<<<trDD, tb, 0, s2>>>(Wo, woh, DD, DD);
    cudaEventRecord(evO, s2);
    split_tr_kernel<<<trDF, tb, 0, s2>>>(W1, w1h, DD, FF);
    cudaEventRecord(ev1p, s2);
    split_tr_kernel<<<trFD, tb, 0, s2>>>(W2, w2h, FF, DD);
    cudaEventRecord(ev2p, s2);

    // ---- main stream ----
    convert_kernel<<<(MR * DD / 4 + 255) / 256, 256>>>(
        (const float4*)x, (__half2*)ah, MR * DD / 4);

    // fused QKV projection (fp16)
    cudaStreamWaitEvent(0, evQKVp, 0);
    gemm_mma<0, 3><<<gQKV, 256, G_SMEM>>>(
        ah, wqkv, bqkv, nullptr, qh, kh, vh, 3 * DD, DD);

    // attention -> fp16 ctx into ah
    attn_mma<<<dim3(8, 128), 256, A_SMEM>>>(qh, kh, vh, mask, ah);

    // output projection + residual LN (emits fp16 x1 into ah)
    cudaStreamWaitEvent(0, evO, 0);
    gemm_mma<0, 0><<<gD, 256, G_SMEM>>>(
        ah, woh, bo, t1, nullptr, nullptr, nullptr, DD, DD);
    residual_ln_kernel<1><<<MR, 256>>>(x, t1, g1, be1, x1, ah);

    // FFN1: relu(x1 @ W1 + bf1) -> fp16 hidden
    cudaStreamWaitEvent(0, ev1p, 0);
    gemm_mma<1, 2><<<gF, 256, G_SMEM>>>(
        ah, w1h, bf1, nullptr, hh, nullptr, nullptr, FF, DD);

    // FFN2 + residual LN
    cudaStreamWaitEvent(0, ev2p, 0);
    gemm_mma<0, 0><<<gD, 256, G_SMEM>>>(
        hh, w2h, bf2, t1, nullptr, nullptr, nullptr, DD, FF);
    residual_ln_kernel<0><<<MR, 256>>>(x1, t1, g2, be2, out, nullptr);
}